// round 14
// baseline (speedup 1.0000x reference)
#include <cuda_runtime.h>
#include <cmath>
#include <cstdint>

#define BSZ   2048          // B_DAYS * STOCKS
#define TT    60
#define HID   256
#define G3    768           // 3*HID
#define DF    6
#define NSAMP 20480         // 4 * K_DAY * STOCKS
#define NDAYS 240
#define KDAY  10
#define NNB   10

// ---------------- device scratch (no allocations allowed) ----------------
__device__ float g_h[2 * BSZ * HID];          // ping-pong raw h (row-major)
__device__ float g_hpk[4 * BSZ * HID];        // ping-pong COMBINED hi+lo frag-packed h
__device__ float g_w0p[2 * G3 * HID];         // Whh0 combined hi+lo frag-packed
__device__ float g_w1p[2 * G3 * HID];
__device__ float g_hs[BSZ * TT * HID];        // layer-0 hidden sequence
__device__ float g_xw1[(size_t)BSZ * TT * G3];// layer-1 input gates
__device__ float g_bias1[G3];
__device__ float g_mb1[BSZ * 512];
__device__ float g_mb2[BSZ * 512];
__device__ float g_mb[BSZ * HID];
__device__ float g_mbday[4 * HID];
__device__ int   g_dayidx[4 * KDAY];
__device__ int   g_rowmap[NSAMP];
__device__ float g_kh[NSAMP * HID];
__device__ float g_khn[NSAMP];
__device__ float g_q[BSZ * HID];
__device__ float g_qn[BSZ];
__device__ float g_cs[(size_t)BSZ * NSAMP];
__device__ float g_vals[BSZ * NNB];
__device__ int   g_nidx[BSZ * NNB];

// ---------------- tf32 helpers ----------------
__device__ __forceinline__ void split_tf32(float x, uint32_t& hi, uint32_t& lo)
{
    uint32_t h;
    asm("cvt.rna.tf32.f32 %0, %1;" : "=r"(h) : "f"(x));
    float rem = x - __uint_as_float(h);
    uint32_t l;
    asm("cvt.rna.tf32.f32 %0, %1;" : "=r"(l) : "f"(rem));
    hi = h; lo = l;
}

__device__ __forceinline__ void mma_tf32(float* d, const uint32_t* a, const uint32_t* b)
{
    asm volatile(
        "mma.sync.aligned.m16n8k8.row.col.f32.tf32.tf32.f32 "
        "{%0,%1,%2,%3}, {%4,%5,%6,%7}, {%8,%9}, {%0,%1,%2,%3};"
        : "+f"(d[0]), "+f"(d[1]), "+f"(d[2]), "+f"(d[3])
        : "r"(a[0]), "r"(a[1]), "r"(a[2]), "r"(a[3]), "r"(b[0]), "r"(b[1]));
}

__device__ __forceinline__ float sigmoidf_(float x) { return 1.f / (1.f + expf(-x)); }

#define CP_ASYNC16(dst, src) \
    asm volatile("cp.async.cg.shared.global [%0], [%1], 16;\n" :: "r"(dst), "l"(src))
#define CP_COMMIT()  asm volatile("cp.async.commit_group;\n")
#define CP_WAIT1()   asm volatile("cp.async.wait_group 1;\n")
#define CP_WAIT0()   asm volatile("cp.async.wait_group 0;\n")

// combined pack index helpers.
// h: 16x8 tile; per lane 8 floats [hi0..3, lo0..3].
// lane=(r%8)*4+(c%4), word=((r>>3)&1)+2*((c>>2)&1); hi at word, lo at word+4.
__device__ __forceinline__ size_t hpk_base(int row, int col)
{
    return ((size_t)(row >> 4) * 32 + (col >> 3)) * 256
         + ((((row & 7) << 2) + (col & 3)) << 3)
         + ((row >> 3) & 1) + (((col >> 2) & 1) << 1);
}
// W: 8(gate)x8(k) tile; per lane 4 floats [bh0,bh1,bl0,bl1].
// lane=(gate%8)*4+(k%4), word=(k>>2)&1; hi at word, lo at word+2.
__device__ __forceinline__ size_t wpk_base(int gate, int k)
{
    return ((size_t)(gate >> 3) * 32 + (k >> 3)) * 128
         + ((((gate & 7) << 2) + (k & 3)) << 2) + ((k >> 2) & 1);
}

// ---------------- 3xTF32 tensor-core GEMM: C[M,N] = A[M,K] @ B[N,K]^T + bias ----
// act: 0 none, 1 leaky(0.01), 2 cosine-normalize by rnorm[m]*cnorm[n]
#define XBM 128
#define XBN 64
#define XBK 32
#define XPAD 36

__global__ void gemm_x(const float* __restrict__ A, const float* __restrict__ B,
                       const float* __restrict__ bias, float* __restrict__ C,
                       int M, int N, int K, int act,
                       const int* __restrict__ rowmap,
                       const float* __restrict__ rnorm, const float* __restrict__ cnorm)
{
    __shared__ float As[XBM][XPAD];   // [m][k]
    __shared__ float Bs[XBN][XPAD];   // [n][k]
    const int bm = blockIdx.y * XBM;
    const int bn = blockIdx.x * XBN;
    const int tid = threadIdx.x;                 // 256
    const int warp = tid >> 5, lane = tid & 31;
    const int wm = (warp & 3) * 32;
    const int wn = (warp >> 2) * 32;
    const int g = lane >> 2, tg = lane & 3;

    float acc[2][4][4];
    #pragma unroll
    for (int a = 0; a < 2; a++)
        #pragma unroll
        for (int b = 0; b < 4; b++)
            #pragma unroll
            for (int c = 0; c < 4; c++) acc[a][b][c] = 0.f;

    for (int k0 = 0; k0 < K; k0 += XBK) {
        #pragma unroll
        for (int i = 0; i < 4; i++) {
            int idx = tid + i * 256;                   // 0..1023
            int r = idx >> 3, c4 = (idx & 7) * 4;
            int arow = bm + r;
            if (rowmap) arow = rowmap[arow];
            float4 v = *(const float4*)(A + (size_t)arow * K + k0 + c4);
            As[r][c4 + 0] = v.x; As[r][c4 + 1] = v.y;
            As[r][c4 + 2] = v.z; As[r][c4 + 3] = v.w;
        }
        #pragma unroll
        for (int i = 0; i < 2; i++) {
            int idx = tid + i * 256;                   // 0..511
            int r = idx >> 3, c4 = (idx & 7) * 4;
            float4 v = *(const float4*)(B + (size_t)(bn + r) * K + k0 + c4);
            Bs[r][c4 + 0] = v.x; Bs[r][c4 + 1] = v.y;
            Bs[r][c4 + 2] = v.z; Bs[r][c4 + 3] = v.w;
        }
        __syncthreads();
        #pragma unroll
        for (int kc = 0; kc < 4; kc++) {
            const int kb = kc * 8;
            uint32_t ahi[2][4], alo[2][4];
            #pragma unroll
            for (int mt = 0; mt < 2; mt++) {
                const int r0 = wm + mt * 16;
                split_tf32(As[r0 + g][kb + tg],         ahi[mt][0], alo[mt][0]);
                split_tf32(As[r0 + g + 8][kb + tg],     ahi[mt][1], alo[mt][1]);
                split_tf32(As[r0 + g][kb + tg + 4],     ahi[mt][2], alo[mt][2]);
                split_tf32(As[r0 + g + 8][kb + tg + 4], ahi[mt][3], alo[mt][3]);
            }
            uint32_t bhi[4][2], blo[4][2];
            #pragma unroll
            for (int nt = 0; nt < 4; nt++) {
                const int c0 = wn + nt * 8;
                split_tf32(Bs[c0 + g][kb + tg],     bhi[nt][0], blo[nt][0]);
                split_tf32(Bs[c0 + g][kb + tg + 4], bhi[nt][1], blo[nt][1]);
            }
            #pragma unroll
            for (int mt = 0; mt < 2; mt++)
                #pragma unroll
                for (int nt = 0; nt < 4; nt++) {
                    mma_tf32(acc[mt][nt], alo[mt], bhi[nt]);
                    mma_tf32(acc[mt][nt], ahi[mt], blo[nt]);
                    mma_tf32(acc[mt][nt], ahi[mt], bhi[nt]);
                }
        }
        __syncthreads();
    }

    #pragma unroll
    for (int mt = 0; mt < 2; mt++) {
        #pragma unroll
        for (int nt = 0; nt < 4; nt++) {
            const int r0 = bm + wm + mt * 16 + g;
            const int c0 = bn + wn + nt * 8 + tg * 2;
            #pragma unroll
            for (int ci = 0; ci < 4; ci++) {
                const int m = r0 + ((ci >> 1) ? 8 : 0);
                const int nn = c0 + (ci & 1);
                float v = acc[mt][nt][ci];
                if (bias) v += bias[nn];
                if (act == 1) {
                    v = (v >= 0.f) ? v : 0.01f * v;
                } else if (act == 2) {
                    float den = rnorm[m] * cnorm[nn];
                    v = (den != 0.f) ? v / den : 0.f;
                }
                C[(size_t)m * N + nn] = v;
            }
        }
    }
}

// ---------------- GRU step kernels v6: combined hi+lo pack, B-reuse tiling ----------------
// CTA: 64 rows x 32 gate-cols (x3 gates). grid (8, 32), 256 thr = 8 warps.
// Warps: 2 m-groups (warp>>2) x 4 n-warps (warp&3); each warp: 2 m-tiles x 3 gate-frags.
// Per ks: 4 LDS.128 (A hi+lo for 2 tiles) + 3 LDS.128 (B combined) + 18 mma.
// LAYER==1 bias contract: xin already has b_ih1+b_hh1 for r,z; b_ih1 for n ->
// epilogue adds ONLY bhh_n. LAYER==0 adds all three bhh parts.
#define GM 64
#define GN 32
#define GK 32

#define SMA 4096            // floats per A buffer (4 mt x 4 kt x 256)
#define SMB 6144            // floats per B buffer (12 gt x 4 kt x 128)
#define OFF_B  (2 * SMA)
#define OFF_EX (2 * SMA + 2 * SMB)
#define SMG_FLT (OFF_EX + 96 + 96 + 32 * 3 * DF + GM * DF)

__device__ __forceinline__ void gru_load_chunk(
    float* sm, const float* __restrict__ hp, const float* __restrict__ wp,
    int bm, int bn, int ch, int buf, int tid)
{
    const int mt0 = bm >> 4;
    const int gtb = bn >> 3;
    // A: 1024 float4 -> 4 iters of 256
    #pragma unroll
    for (int j = 0; j < 4; j++) {
        int idx = tid + j * 256;
        int mt = idx >> 8, rem = idx & 255;
        int ktl = rem >> 6, f4 = rem & 63;
        size_t g4 = (((size_t)(mt0 + mt) * 32 + (ch * 4 + ktl)) * 64 + f4) * 4;
        uint32_t d = (uint32_t)__cvta_generic_to_shared(sm + buf * SMA + idx * 4);
        CP_ASYNC16(d, hp + g4);
    }
    // B: 1536 float4 -> 6 iters of 256
    #pragma unroll
    for (int j = 0; j < 6; j++) {
        int idx = tid + j * 256;
        int lgt = idx >> 7, rem = idx & 127;
        int ktl = rem >> 5, f4 = rem & 31;
        int gt = (lgt >> 2) * 32 + gtb + (lgt & 3);
        size_t g4 = (((size_t)gt * 32 + (ch * 4 + ktl)) * 32 + f4) * 4;
        uint32_t d = (uint32_t)__cvta_generic_to_shared(sm + OFF_B + buf * SMB + idx * 4);
        CP_ASYNC16(d, wp + g4);
    }
    CP_COMMIT();
}

template<int LAYER>
__global__ void __launch_bounds__(256) gru_v6(
    const float* __restrict__ hin, const float* __restrict__ hin_pk,
    float* __restrict__ hout, float* __restrict__ hout_pk,
    const float* __restrict__ wp,
    const float* __restrict__ bhh, const float* __restrict__ xin,
    const float* __restrict__ Wih, const float* __restrict__ bih, int t)
{
    extern __shared__ float sm[];
    float* bih_s = sm + OFF_EX;         // [96] (layer0)
    float* bhh_s = bih_s + 96;          // [96]
    float* wih_s = bhh_s + 96;          // [32][3*DF] (layer0)
    float* xs    = wih_s + 32 * 3 * DF; // [64][DF] (layer0)

    const int tid = threadIdx.x;
    const int warp = tid >> 5, lane = tid & 31;
    const int mw = warp >> 2;                // 2 m-groups of 32 rows (2 m-tiles each)
    const int nw = warp & 3;                 // 4 n-warps of 8 cols (per gate)
    const int g = lane >> 2, tg = lane & 3;
    const int bn = blockIdx.x * GN;
    const int bm = blockIdx.y * GM;

    if (tid < 96) {
        const int gg = tid >> 5, c = tid & 31;
        bhh_s[tid] = bhh[gg * HID + bn + c];
        if (LAYER == 0) bih_s[tid] = bih[gg * HID + bn + c];
    }
    if (LAYER == 0) {
        for (int i = tid; i < 32 * 3 * DF; i += 256) {
            const int c = i / (3 * DF), r = i % (3 * DF);
            wih_s[i] = Wih[((r / DF) * HID + bn + c) * DF + (r % DF)];
        }
        for (int i = tid; i < GM * DF; i += 256) {
            const int r = i / DF, f = i % DF;
            xs[i] = xin[(bm + r) * (DF * TT) + f * TT + t];
        }
    }

    gru_load_chunk(sm, hin_pk, wp, bm, bn, 0, 0, tid);

    float acc[3][2][4];
    #pragma unroll
    for (int a = 0; a < 3; a++)
        #pragma unroll
        for (int b = 0; b < 2; b++)
            #pragma unroll
            for (int d = 0; d < 4; d++) acc[a][b][d] = 0.f;

    #pragma unroll
    for (int ch = 0; ch < 8; ch++) {
        if (ch < 7) { gru_load_chunk(sm, hin_pk, wp, bm, bn, ch + 1, (ch + 1) & 1, tid); CP_WAIT1(); }
        else        { CP_WAIT0(); }
        __syncthreads();

        const float* Ab = sm + (ch & 1) * SMA;
        const float* Bb = sm + OFF_B + (ch & 1) * SMB;

        #pragma unroll
        for (int ks = 0; ks < 4; ks++) {
            uint32_t ah[2][4], al[2][4];
            #pragma unroll
            for (int i = 0; i < 2; i++) {
                const int fo = ((mw * 2 + i) * 4 + ks) * 256 + lane * 8;
                uint4 vh = *(const uint4*)(Ab + fo);
                uint4 vl = *(const uint4*)(Ab + fo + 4);
                ah[i][0] = vh.x; ah[i][1] = vh.y; ah[i][2] = vh.z; ah[i][3] = vh.w;
                al[i][0] = vl.x; al[i][1] = vl.y; al[i][2] = vl.z; al[i][3] = vl.w;
            }
            #pragma unroll
            for (int gg = 0; gg < 3; gg++) {
                const int fo = ((gg * 4 + nw) * 4 + ks) * 128 + lane * 4;
                uint4 vb = *(const uint4*)(Bb + fo);
                uint32_t bh[2] = { vb.x, vb.y };
                uint32_t bl[2] = { vb.z, vb.w };
                #pragma unroll
                for (int i = 0; i < 2; i++) {
                    mma_tf32(acc[gg][i], al[i], bh);
                    mma_tf32(acc[gg][i], ah[i], bl);
                    mma_tf32(acc[gg][i], ah[i], bh);
                }
            }
        }
        __syncthreads();
    }

    #pragma unroll
    for (int i = 0; i < 2; i++) {
        #pragma unroll
        for (int ci = 0; ci < 4; ci++) {
            const int rl = mw * 32 + i * 16 + g + ((ci >> 1) ? 8 : 0);
            const int cl = nw * 8 + tg * 2 + (ci & 1);
            const int row = bm + rl, col = bn + cl;
            float r, z, nn;
            if (LAYER == 0) {
                float xr = bih_s[cl], xz = bih_s[32 + cl], xn = bih_s[64 + cl];
                #pragma unroll
                for (int f = 0; f < DF; f++) {
                    const float xv = xs[rl * DF + f];
                    xr += xv * wih_s[cl * 3 * DF + f];
                    xz += xv * wih_s[cl * 3 * DF + DF + f];
                    xn += xv * wih_s[cl * 3 * DF + 2 * DF + f];
                }
                r  = sigmoidf_(xr + acc[0][i][ci] + bhh_s[cl]);
                z  = sigmoidf_(xz + acc[1][i][ci] + bhh_s[32 + cl]);
                nn = tanhf(xn + r * (acc[2][i][ci] + bhh_s[64 + cl]));
            } else {
                const size_t xb = ((size_t)row * TT + t) * G3 + col;
                const float xr = xin[xb];
                const float xz = xin[xb + HID];
                const float xn = xin[xb + 2 * HID];
                r  = sigmoidf_(xr + acc[0][i][ci]);
                z  = sigmoidf_(xz + acc[1][i][ci]);
                nn = tanhf(xn + r * (acc[2][i][ci] + bhh_s[64 + cl]));
            }
            const float ho = hin[(size_t)row * HID + col];
            const float hv = (1.f - z) * nn + z * ho;
            hout[(size_t)row * HID + col] = hv;
            uint32_t hi, lo; split_tf32(hv, hi, lo);
            const size_t pb = hpk_base(row, col);
            hout_pk[pb]     = __uint_as_float(hi);
            hout_pk[pb + 4] = __uint_as_float(lo);
            if (LAYER == 0) g_hs[((size_t)row * TT + t) * HID + col] = hv;
        }
    }
}

// ---------------- small kernels ----------------
__global__ void split_mat_packed(const float* __restrict__ in, float* __restrict__ op)
{
    const int i = blockIdx.x * 256 + threadIdx.x;
    if (i < G3 * HID) {
        const int gate = i >> 8, k = i & 255;
        uint32_t h, l;
        split_tf32(in[i], h, l);
        const size_t p = wpk_base(gate, k);
        op[p]     = __uint_as_float(h);
        op[p + 2] = __uint_as_float(l);
    }
}

__global__ void bias_combine(const float* __restrict__ bih, const float* __restrict__ bhh,
                             float* __restrict__ out)
{
    const int i = blockIdx.x * 256 + threadIdx.x;
    if (i < G3) out[i] = bih[i] + ((i < 512) ? bhh[i] : 0.f);
}

__global__ void mb_day_mean()
{
    const int b = blockIdx.x, h = threadIdx.x;
    float s = 0.f;
    for (int st = 0; st < 512; st++) s += g_mb[(b * 512 + st) * HID + h];
    g_mbday[b * HID + h] = s * (1.f / 512.f);
}

__global__ void day_topk(const float* __restrict__ thd)
{
    const int b = blockIdx.x;
    const int d = threadIdx.x;
    __shared__ float sim[NDAYS];
    const float* mbd = g_mbday + b * HID;
    float xn = 0.f;
    for (int i = 0; i < HID; i++) { float v = mbd[i]; xn += v * v; }
    xn = sqrtf(xn);
    if (d < NDAYS) {
        const float* yr = thd + d * HID;
        float yn = 0.f, dot = 0.f;
        for (int i = 0; i < HID; i++) { float y = yr[i]; yn += y * y; dot += mbd[i] * y; }
        const float den = xn * sqrtf(yn);
        sim[d] = (den != 0.f) ? dot / den : 0.f;
    }
    __syncthreads();
    if (d == 0) {
        for (int kk = 0; kk < KDAY; kk++) {
            float best = -1e30f; int bi = 0;
            for (int q = 0; q < NDAYS; q++)
                if (sim[q] > best) { best = sim[q]; bi = q; }
            g_dayidx[b * KDAY + kk] = bi;
            sim[bi] = -1e30f;
        }
    }
}

__global__ void make_rowmap()
{
    const int m = blockIdx.x * 256 + threadIdx.x;
    if (m < NSAMP) g_rowmap[m] = g_dayidx[m >> 9] * 512 + (m & 511);
}

__global__ void rownorm256(const float* __restrict__ X, float* __restrict__ out, int R)
{
    const int warp = (blockIdx.x * blockDim.x + threadIdx.x) >> 5;
    const int lane = threadIdx.x & 31;
    if (warp >= R) return;
    const float* r = X + (size_t)warp * HID;
    float s = 0.f;
    for (int i = lane; i < HID; i += 32) { float v = r[i]; s += v * v; }
    #pragma unroll
    for (int o = 16; o > 0; o >>= 1) s += __shfl_xor_sync(0xffffffffu, s, o);
    if (lane == 0) out[warp] = sqrtf(s);
}

__global__ void neigh_topk()
{
    const int n = blockIdx.x;
    const int tid = threadIdx.x;
    const float* row = g_cs + (size_t)n * NSAMP;

    float tv[NNB]; int ti[NNB];
    #pragma unroll
    for (int i = 0; i < NNB; i++) { tv[i] = -1e30f; ti[i] = 0x7fffffff; }

    for (int it = 0; it < NSAMP / 256; it++) {
        const int idx = tid + it * 256;
        const float v = row[idx];
        if (v > tv[NNB - 1]) {
            int p = NNB - 1;
            while (p > 0 && tv[p - 1] < v) { tv[p] = tv[p - 1]; ti[p] = ti[p - 1]; p--; }
            tv[p] = v; ti[p] = idx;
        }
    }

    __shared__ float sval[256 * NNB];
    __shared__ int   sidx[256 * NNB];
    __shared__ float rv[256];
    __shared__ int   rp[256];
    #pragma unroll
    for (int i = 0; i < NNB; i++) { sval[tid * NNB + i] = tv[i]; sidx[tid * NNB + i] = ti[i]; }
    __syncthreads();

    for (int kk = 0; kk < NNB; kk++) {
        float best = -1e30f; int bp = tid * NNB;
        #pragma unroll
        for (int i = 0; i < NNB; i++) {
            const float v = sval[tid * NNB + i];
            if (v > best) { best = v; bp = tid * NNB + i; }
        }
        rv[tid] = best; rp[tid] = bp;
        __syncthreads();
        for (int s = 128; s > 0; s >>= 1) {
            if (tid < s && rv[tid + s] > rv[tid]) { rv[tid] = rv[tid + s]; rp[tid] = rp[tid + s]; }
            __syncthreads();
        }
        if (tid == 0) {
            const int p = rp[0];
            g_vals[n * NNB + kk] = rv[0];
            g_nidx[n * NNB + kk] = sidx[p];
            sval[p] = -1e30f;
        }
        __syncthreads();
    }
}

__global__ void agg_fc(const float* __restrict__ fc_W, const float* __restrict__ fc_b,
                       float* __restrict__ y)
{
    const int n = blockIdx.x, h = threadIdx.x;
    float agg = 0.f;
    #pragma unroll
    for (int k = 0; k < NNB; k++) {
        const float v = g_vals[n * NNB + k] * (1.f / NNB);
        const int id = g_nidx[n * NNB + k];
        agg += v * g_kh[(size_t)id * HID + h];
    }
    float part = fc_W[h] * g_mb[n * HID + h] + fc_W[HID + h] * agg;
    __shared__ float red[256];
    red[h] = part;
    __syncthreads();
    for (int s = 128; s > 0; s >>= 1) {
        if (h < s) red[h] += red[h + s];
        __syncthreads();
    }
    if (h == 0) y[n] = red[0] + fc_b[0];
}

// ---------------- host ----------------
extern "C" void kernel_launch(void* const* d_in, const int* in_sizes, int n_in,
                              void* d_out, int out_size)
{
    const float* inp       = (const float*)d_in[0];
    const float* train_hid = (const float*)d_in[1];
    const float* thd       = (const float*)d_in[2];
    const float* W_ih0     = (const float*)d_in[3];
    const float* W_hh0     = (const float*)d_in[4];
    const float* b_ih0     = (const float*)d_in[5];
    const float* b_hh0     = (const float*)d_in[6];
    const float* W_ih1     = (const float*)d_in[7];
    const float* W_hh1     = (const float*)d_in[8];
    const float* b_ih1     = (const float*)d_in[9];
    const float* b_hh1     = (const float*)d_in[10];
    const float* lin0_W    = (const float*)d_in[11];
    const float* lin0_b    = (const float*)d_in[12];
    const float* lin1_W    = (const float*)d_in[13];
    const float* lin1_b    = (const float*)d_in[14];
    const float* lin2_W    = (const float*)d_in[15];
    const float* lin2_b    = (const float*)d_in[16];
    const float* proj1_W   = (const float*)d_in[17];
    const float* proj2_W   = (const float*)d_in[18];
    const float* fc_W      = (const float*)d_in[19];
    const float* fc_b      = (const float*)d_in[20];
    (void)in_sizes; (void)n_in; (void)out_size;

    float *p_h, *p_hpk, *p_w0p, *p_w1p;
    float *p_hs, *p_xw1, *p_bias1, *p_mb1, *p_mb2, *p_mb, *p_kh, *p_khn, *p_q, *p_qn, *p_cs;
    int *p_rowmap;
    cudaGetSymbolAddress((void**)&p_h, g_h);
    cudaGetSymbolAddress((void**)&p_hpk, g_hpk);
    cudaGetSymbolAddress((void**)&p_w0p, g_w0p);
    cudaGetSymbolAddress((void**)&p_w1p, g_w1p);
    cudaGetSymbolAddress((void**)&p_hs, g_hs);
    cudaGetSymbolAddress((void**)&p_xw1, g_xw1);
    cudaGetSymbolAddress((void**)&p_bias1, g_bias1);
    cudaGetSymbolAddress((void**)&p_mb1, g_mb1);
    cudaGetSymbolAddress((void**)&p_mb2, g_mb2);
    cudaGetSymbolAddress((void**)&p_mb, g_mb);
    cudaGetSymbolAddress((void**)&p_kh, g_kh);
    cudaGetSymbolAddress((void**)&p_khn, g_khn);
    cudaGetSymbolAddress((void**)&p_q, g_q);
    cudaGetSymbolAddress((void**)&p_qn, g_qn);
    cudaGetSymbolAddress((void**)&p_cs, g_cs);
    cudaGetSymbolAddress((void**)&p_rowmap, g_rowmap);

    const int smg = SMG_FLT * 4;
    cudaFuncSetAttribute(gru_v6<0>, cudaFuncAttributeMaxDynamicSharedMemorySize, smg);
    cudaFuncSetAttribute(gru_v6<1>, cudaFuncAttributeMaxDynamicSharedMemorySize, smg);

    const size_t HN  = (size_t)BSZ * HID;      // raw h buffer stride
    const size_t HPN = 2 * HN;                 // packed (hi+lo) buffer stride
    const dim3 gru_grid(HID / GN, BSZ / GM);   // (8, 32)

    // ---- pre-split recurrent weights into combined frag-packed hi/lo ----
    split_mat_packed<<<(G3 * HID + 255) / 256, 256>>>(W_hh0, p_w0p);
    split_mat_packed<<<(G3 * HID + 255) / 256, 256>>>(W_hh1, p_w1p);

    // ---- GRU layer 0 ----
    cudaMemsetAsync(p_h, 0, HN * sizeof(float));
    cudaMemsetAsync(p_hpk, 0, HPN * sizeof(float));
    for (int t = 0; t < TT; t++) {
        const int pr = t & 1, pw = pr ^ 1;
        gru_v6<0><<<gru_grid, 256, smg>>>(
            p_h + pr * HN, p_hpk + pr * HPN,
            p_h + pw * HN, p_hpk + pw * HPN,
            p_w0p, b_hh0, inp, W_ih0, b_ih0, t);
    }

    // ---- layer-1 input gates: one big 3xTF32 GEMM (combined bias) ----
    bias_combine<<<3, 256>>>(b_ih1, b_hh1, p_bias1);
    gemm_x<<<dim3(G3 / XBN, (BSZ * TT) / XBM), 256>>>(p_hs, W_ih1, p_bias1, p_xw1,
                                                      BSZ * TT, G3, HID, 0, nullptr, nullptr, nullptr);

    // ---- GRU layer 1 ----
    cudaMemsetAsync(p_h, 0, HN * sizeof(float));
    cudaMemsetAsync(p_hpk, 0, HPN * sizeof(float));
    for (int t = 0; t < TT; t++) {
        const int pr = t & 1, pw = pr ^ 1;
        gru_v6<1><<<gru_grid, 256, smg>>>(
            p_h + pr * HN, p_hpk + pr * HPN,
            p_h + pw * HN, p_hpk + pw * HPN,
            p_w1p, b_hh1, p_xw1, nullptr, nullptr, t);
    }
    // t=59 writes parity 0 -> final h at p_h

    // ---- MLP (leaky relu) ----
    gemm_x<<<dim3(512 / XBN, BSZ / XBM), 256>>>(p_h, lin0_W, lin0_b, p_mb1,
                                                BSZ, 512, HID, 1, nullptr, nullptr, nullptr);
    gemm_x<<<dim3(512 / XBN, BSZ / XBM), 256>>>(p_mb1, lin1_W, lin1_b, p_mb2,
                                                BSZ, 512, 512, 1, nullptr, nullptr, nullptr);
    gemm_x<<<dim3(HID / XBN, BSZ / XBM), 256>>>(p_mb2, lin2_W, lin2_b, p_mb,
                                                BSZ, HID, 512, 1, nullptr, nullptr, nullptr);

    // ---- day similarity + gather ----
    mb_day_mean<<<4, HID>>>();
    day_topk<<<4, 256>>>(thd);
    make_rowmap<<<NSAMP / 256, 256>>>();
    gemm_x<<<dim3(HID / XBN, NSAMP / XBM), 256>>>(train_hid, proj2_W, nullptr, p_kh,
                                                  NSAMP, HID, HID, 0, p_rowmap, nullptr, nullptr);
    rownorm256<<<(NSAMP * 32) / 256, 256>>>(p_kh, p_khn, NSAMP);

    // ---- queries + cosine sim + neighbor aggregation ----
    gemm_x<<<dim3(HID / XBN, BSZ / XBM), 256>>>(p_mb, proj1_W, nullptr, p_q,
                                                BSZ, HID, HID, 0, nullptr, nullptr, nullptr);
    rownorm256<<<(BSZ * 32) / 256, 256>>>(p_q, p_qn, BSZ);
    gemm_x<<<dim3(NSAMP / XBN, BSZ / XBM), 256>>>(p_q, p_kh, nullptr, p_cs,
                                                  BSZ, NSAMP, HID, 2, nullptr, p_qn, p_khn);
    neigh_topk<<<BSZ, 256>>>();
    agg_fc<<<BSZ, 256>>>(fc_W, fc_b, (float*)d_out);
}

// round 15
// speedup vs baseline: 1.0464x; 1.0464x over previous
#include <cuda_runtime.h>
#include <cmath>
#include <cstdint>

#define BSZ   2048          // B_DAYS * STOCKS
#define TT    60
#define HID   256
#define G3    768           // 3*HID
#define DF    6
#define NSAMP 20480         // 4 * K_DAY * STOCKS
#define NDAYS 240
#define KDAY  10
#define NNB   10

// ---------------- device scratch (no allocations allowed) ----------------
__device__ float g_h[2 * BSZ * HID];          // ping-pong raw h (row-major)
__device__ float g_hhi[2 * BSZ * HID];        // ping-pong tf32-hi of h (FRAG-PACKED)
__device__ float g_hlo[2 * BSZ * HID];        // ping-pong tf32-lo of h (FRAG-PACKED)
__device__ float g_w0hi[G3 * HID];            // Whh0 hi (FRAG-PACKED)
__device__ float g_w0lo[G3 * HID];
__device__ float g_w1hi[G3 * HID];
__device__ float g_w1lo[G3 * HID];
__device__ float g_hs[BSZ * TT * HID];        // layer-0 hidden sequence
__device__ float g_xw1[(size_t)BSZ * TT * G3];// layer-1 input gates
__device__ float g_bias1[G3];
__device__ float g_mb1[BSZ * 512];
__device__ float g_mb2[BSZ * 512];
__device__ float g_mb[BSZ * HID];
__device__ float g_mbday[4 * HID];
__device__ int   g_dayidx[4 * KDAY];
__device__ int   g_rowmap[NSAMP];
__device__ float g_kh[NSAMP * HID];
__device__ float g_khn[NSAMP];
__device__ float g_q[BSZ * HID];
__device__ float g_qn[BSZ];
__device__ float g_cs[(size_t)BSZ * NSAMP];
__device__ float g_vals[BSZ * NNB];
__device__ int   g_nidx[BSZ * NNB];

// ---------------- tf32 helpers ----------------
__device__ __forceinline__ void split_tf32(float x, uint32_t& hi, uint32_t& lo)
{
    uint32_t h;
    asm("cvt.rna.tf32.f32 %0, %1;" : "=r"(h) : "f"(x));
    float rem = x - __uint_as_float(h);
    uint32_t l;
    asm("cvt.rna.tf32.f32 %0, %1;" : "=r"(l) : "f"(rem));
    hi = h; lo = l;
}

__device__ __forceinline__ void mma_tf32(float* d, const uint32_t* a, const uint32_t* b)
{
    asm volatile(
        "mma.sync.aligned.m16n8k8.row.col.f32.tf32.tf32.f32 "
        "{%0,%1,%2,%3}, {%4,%5,%6,%7}, {%8,%9}, {%0,%1,%2,%3};"
        : "+f"(d[0]), "+f"(d[1]), "+f"(d[2]), "+f"(d[3])
        : "r"(a[0]), "r"(a[1]), "r"(a[2]), "r"(a[3]), "r"(b[0]), "r"(b[1]));
}

__device__ __forceinline__ float sigmoidf_(float x) { return 1.f / (1.f + expf(-x)); }

#define CP_ASYNC16(dst, src) \
    asm volatile("cp.async.cg.shared.global [%0], [%1], 16;\n" :: "r"(dst), "l"(src))
#define CP_COMMIT()  asm volatile("cp.async.commit_group;\n")
#define CP_WAIT1()   asm volatile("cp.async.wait_group 1;\n")
#define CP_WAIT0()   asm volatile("cp.async.wait_group 0;\n")

// packed index helpers.
// A-frag pack (h): 16x8 tile -> [lane][word]: lane=(r%8)*4+(c%4), word=((r>>3)&1)+2*((c>>2)&1)
__device__ __forceinline__ size_t hpack_idx(int row, int col)
{
    return ((size_t)(row >> 4) * 32 + (col >> 3)) * 128
         + (((row & 7) << 2) + (col & 3)) * 4
         + ((row >> 3) & 1) + (((col >> 2) & 1) << 1);
}
// B-frag pack (W): 8(gate)x8(k) tile -> [lane][word]: lane=(gate%8)*4+(k%4), word=(k>>2)&1
__device__ __forceinline__ size_t wpack_idx(int gate, int k)
{
    return ((size_t)(gate >> 3) * 32 + (k >> 3)) * 64
         + (((gate & 7) << 2) + (k & 3)) * 2 + ((k >> 2) & 1);
}

// ---------------- 3xTF32 tensor-core GEMM: C[M,N] = A[M,K] @ B[N,K]^T + bias ----
// act: 0 none, 1 leaky(0.01), 2 cosine-normalize by rnorm[m]*cnorm[n]
#define XBM 128
#define XBN 64
#define XBK 32
#define XPAD 36

__global__ void gemm_x(const float* __restrict__ A, const float* __restrict__ B,
                       const float* __restrict__ bias, float* __restrict__ C,
                       int M, int N, int K, int act,
                       const int* __restrict__ rowmap,
                       const float* __restrict__ rnorm, const float* __restrict__ cnorm)
{
    __shared__ float As[XBM][XPAD];   // [m][k]
    __shared__ float Bs[XBN][XPAD];   // [n][k]
    const int bm = blockIdx.y * XBM;
    const int bn = blockIdx.x * XBN;
    const int tid = threadIdx.x;                 // 256
    const int warp = tid >> 5, lane = tid & 31;
    const int wm = (warp & 3) * 32;
    const int wn = (warp >> 2) * 32;
    const int g = lane >> 2, tg = lane & 3;

    float acc[2][4][4];
    #pragma unroll
    for (int a = 0; a < 2; a++)
        #pragma unroll
        for (int b = 0; b < 4; b++)
            #pragma unroll
            for (int c = 0; c < 4; c++) acc[a][b][c] = 0.f;

    for (int k0 = 0; k0 < K; k0 += XBK) {
        #pragma unroll
        for (int i = 0; i < 4; i++) {
            int idx = tid + i * 256;                   // 0..1023
            int r = idx >> 3, c4 = (idx & 7) * 4;
            int arow = bm + r;
            if (rowmap) arow = rowmap[arow];
            float4 v = *(const float4*)(A + (size_t)arow * K + k0 + c4);
            As[r][c4 + 0] = v.x; As[r][c4 + 1] = v.y;
            As[r][c4 + 2] = v.z; As[r][c4 + 3] = v.w;
        }
        #pragma unroll
        for (int i = 0; i < 2; i++) {
            int idx = tid + i * 256;                   // 0..511
            int r = idx >> 3, c4 = (idx & 7) * 4;
            float4 v = *(const float4*)(B + (size_t)(bn + r) * K + k0 + c4);
            Bs[r][c4 + 0] = v.x; Bs[r][c4 + 1] = v.y;
            Bs[r][c4 + 2] = v.z; Bs[r][c4 + 3] = v.w;
        }
        __syncthreads();
        #pragma unroll
        for (int kc = 0; kc < 4; kc++) {
            const int kb = kc * 8;
            uint32_t ahi[2][4], alo[2][4];
            #pragma unroll
            for (int mt = 0; mt < 2; mt++) {
                const int r0 = wm + mt * 16;
                split_tf32(As[r0 + g][kb + tg],         ahi[mt][0], alo[mt][0]);
                split_tf32(As[r0 + g + 8][kb + tg],     ahi[mt][1], alo[mt][1]);
                split_tf32(As[r0 + g][kb + tg + 4],     ahi[mt][2], alo[mt][2]);
                split_tf32(As[r0 + g + 8][kb + tg + 4], ahi[mt][3], alo[mt][3]);
            }
            uint32_t bhi[4][2], blo[4][2];
            #pragma unroll
            for (int nt = 0; nt < 4; nt++) {
                const int c0 = wn + nt * 8;
                split_tf32(Bs[c0 + g][kb + tg],     bhi[nt][0], blo[nt][0]);
                split_tf32(Bs[c0 + g][kb + tg + 4], bhi[nt][1], blo[nt][1]);
            }
            #pragma unroll
            for (int mt = 0; mt < 2; mt++)
                #pragma unroll
                for (int nt = 0; nt < 4; nt++) {
                    mma_tf32(acc[mt][nt], alo[mt], bhi[nt]);
                    mma_tf32(acc[mt][nt], ahi[mt], blo[nt]);
                    mma_tf32(acc[mt][nt], ahi[mt], bhi[nt]);
                }
        }
        __syncthreads();
    }

    #pragma unroll
    for (int mt = 0; mt < 2; mt++) {
        #pragma unroll
        for (int nt = 0; nt < 4; nt++) {
            const int r0 = bm + wm + mt * 16 + g;
            const int c0 = bn + wn + nt * 8 + tg * 2;
            #pragma unroll
            for (int ci = 0; ci < 4; ci++) {
                const int m = r0 + ((ci >> 1) ? 8 : 0);
                const int nn = c0 + (ci & 1);
                float v = acc[mt][nt][ci];
                if (bias) v += bias[nn];
                if (act == 1) {
                    v = (v >= 0.f) ? v : 0.01f * v;
                } else if (act == 2) {
                    float den = rnorm[m] * cnorm[nn];
                    v = (den != 0.f) ? v / den : 0.f;
                }
                C[(size_t)m * N + nn] = v;
            }
        }
    }
}

// ---------------- GRU step kernels v7: v5 layout + B-reuse warp tiling ----------------
// CTA: 64 rows x 32 gate-cols (x3 gates). grid (8, 32), 256 thr = 8 warps.
// Warps: 2 m-groups (warp>>2, 2 m-tiles each) x 4 n-warps (warp&3, 1 B-frag/gate).
// Per ks: 4 LDS.128 (A hi/lo x 2 tiles) + 6 LDS.64 (B hi/lo x 3 gates) + 18 mma.
// All smem strides conflict-free (lane*4 / lane*2 floats), identical to v5.
// LAYER==1 bias contract: xin already has b_ih1+b_hh1 for r,z; b_ih1 for n ->
// epilogue adds ONLY bhh_n. LAYER==0 adds all three bhh parts.
#define GM 64
#define GN 32
#define GK 32

#define SMA 2048            // floats per A buffer per array (4 mt x 4 kt x 32 x 4)
#define SMB 3072            // floats per B buffer per array (12 gt x 4 kt x 32 x 2)
#define OFF_AL (2 * SMA)
#define OFF_BH (4 * SMA)
#define OFF_BL (4 * SMA + 2 * SMB)
#define OFF_EX (4 * SMA + 4 * SMB)
#define SMG_FLT (OFF_EX + 96 + 96 + 32 * 3 * DF + GM * DF)

__device__ __forceinline__ void gru_load_chunk(
    float* sm, const float* __restrict__ hhi, const float* __restrict__ hlo,
    const float* __restrict__ whi, const float* __restrict__ wlo,
    int bm, int bn, int ch, int buf, int tid)
{
    const int mt0 = bm >> 4;
    const int gtb = bn >> 3;
    // A: 512 float4 per array -> 2 iters of 256
    #pragma unroll
    for (int j = 0; j < 2; j++) {
        int idx = tid + j * 256;
        int mt = idx >> 7, rem = idx & 127;
        int ktl = rem >> 5, ln = rem & 31;
        size_t g4 = (((size_t)(mt0 + mt) * 32 + (ch * 4 + ktl)) * 32 + ln) * 4;
        uint32_t d1 = (uint32_t)__cvta_generic_to_shared(sm + buf * SMA + idx * 4);
        CP_ASYNC16(d1, hhi + g4);
        uint32_t d2 = (uint32_t)__cvta_generic_to_shared(sm + OFF_AL + buf * SMA + idx * 4);
        CP_ASYNC16(d2, hlo + g4);
    }
    // B: 768 float4 per array -> 3 iters of 256
    #pragma unroll
    for (int j = 0; j < 3; j++) {
        int idx = tid + j * 256;
        int lgt = idx >> 6, rem = idx & 63;
        int ktl = rem >> 4, f4l = rem & 15;
        int gt = (lgt >> 2) * 32 + gtb + (lgt & 3);
        size_t g4 = (((size_t)gt * 32 + (ch * 4 + ktl)) * 16 + f4l) * 4;
        uint32_t d1 = (uint32_t)__cvta_generic_to_shared(sm + OFF_BH + buf * SMB + idx * 4);
        CP_ASYNC16(d1, whi + g4);
        uint32_t d2 = (uint32_t)__cvta_generic_to_shared(sm + OFF_BL + buf * SMB + idx * 4);
        CP_ASYNC16(d2, wlo + g4);
    }
    CP_COMMIT();
}

template<int LAYER>
__global__ void __launch_bounds__(256) gru_v7(
    const float* __restrict__ hin, const float* __restrict__ hin_hi,
    const float* __restrict__ hin_lo, float* __restrict__ hout,
    float* __restrict__ hout_hi, float* __restrict__ hout_lo,
    const float* __restrict__ whi, const float* __restrict__ wlo,
    const float* __restrict__ bhh, const float* __restrict__ xin,
    const float* __restrict__ Wih, const float* __restrict__ bih, int t)
{
    extern __shared__ float sm[];
    float* bih_s = sm + OFF_EX;         // [96] (layer0)
    float* bhh_s = bih_s + 96;          // [96]
    float* wih_s = bhh_s + 96;          // [32][3*DF] (layer0)
    float* xs    = wih_s + 32 * 3 * DF; // [64][DF] (layer0)

    const int tid = threadIdx.x;
    const int warp = tid >> 5, lane = tid & 31;
    const int mw = warp >> 2;                // 2 m-groups (2 m-tiles of 16 rows each)
    const int nw = warp & 3;                 // 4 n-warps (one 8-col B-frag per gate)
    const int g = lane >> 2, tg = lane & 3;
    const int bn = blockIdx.x * GN;
    const int bm = blockIdx.y * GM;

    if (tid < 96) {
        const int gg = tid >> 5, c = tid & 31;
        bhh_s[tid] = bhh[gg * HID + bn + c];
        if (LAYER == 0) bih_s[tid] = bih[gg * HID + bn + c];
    }
    if (LAYER == 0) {
        for (int i = tid; i < 32 * 3 * DF; i += 256) {
            const int c = i / (3 * DF), r = i % (3 * DF);
            wih_s[i] = Wih[((r / DF) * HID + bn + c) * DF + (r % DF)];
        }
        for (int i = tid; i < GM * DF; i += 256) {
            const int r = i / DF, f = i % DF;
            xs[i] = xin[(bm + r) * (DF * TT) + f * TT + t];
        }
    }

    gru_load_chunk(sm, hin_hi, hin_lo, whi, wlo, bm, bn, 0, 0, tid);

    float acc[3][2][4];
    #pragma unroll
    for (int a = 0; a < 3; a++)
        #pragma unroll
        for (int b = 0; b < 2; b++)
            #pragma unroll
            for (int d = 0; d < 4; d++) acc[a][b][d] = 0.f;

    #pragma unroll
    for (int ch = 0; ch < 8; ch++) {
        if (ch < 7) { gru_load_chunk(sm, hin_hi, hin_lo, whi, wlo, bm, bn, ch + 1, (ch + 1) & 1, tid); CP_WAIT1(); }
        else        { CP_WAIT0(); }
        __syncthreads();

        const float* Ah = sm + (ch & 1) * SMA;
        const float* Al = sm + OFF_AL + (ch & 1) * SMA;
        const float* Bh = sm + OFF_BH + (ch & 1) * SMB;
        const float* Bl = sm + OFF_BL + (ch & 1) * SMB;

        #pragma unroll
        for (int ks = 0; ks < 4; ks++) {
            uint32_t ah[2][4], al[2][4];
            #pragma unroll
            for (int i = 0; i < 2; i++) {
                const int fa = (((mw * 2 + i) * 4 + ks) * 32 + lane) * 4;
                uint4 vh = *(const uint4*)(Ah + fa);
                uint4 vl = *(const uint4*)(Al + fa);
                ah[i][0] = vh.x; ah[i][1] = vh.y; ah[i][2] = vh.z; ah[i][3] = vh.w;
                al[i][0] = vl.x; al[i][1] = vl.y; al[i][2] = vl.z; al[i][3] = vl.w;
            }
            #pragma unroll
            for (int gg = 0; gg < 3; gg++) {
                const int lgt = gg * 4 + nw;
                const int fo = (lgt * 4 + ks) * 64 + lane * 2;
                uint2 vbh = *(const uint2*)(Bh + fo);
                uint2 vbl = *(const uint2*)(Bl + fo);
                uint32_t bh[2] = { vbh.x, vbh.y };
                uint32_t bl[2] = { vbl.x, vbl.y };
                #pragma unroll
                for (int i = 0; i < 2; i++) {
                    mma_tf32(acc[gg][i], al[i], bh);
                    mma_tf32(acc[gg][i], ah[i], bl);
                    mma_tf32(acc[gg][i], ah[i], bh);
                }
            }
        }
        __syncthreads();
    }

    #pragma unroll
    for (int i = 0; i < 2; i++) {
        #pragma unroll
        for (int ci = 0; ci < 4; ci++) {
            const int rl = mw * 32 + i * 16 + g + ((ci >> 1) ? 8 : 0);
            const int cl = nw * 8 + tg * 2 + (ci & 1);
            const int row = bm + rl, col = bn + cl;
            float r, z, nn;
            if (LAYER == 0) {
                float xr = bih_s[cl], xz = bih_s[32 + cl], xn = bih_s[64 + cl];
                #pragma unroll
                for (int f = 0; f < DF; f++) {
                    const float xv = xs[rl * DF + f];
                    xr += xv * wih_s[cl * 3 * DF + f];
                    xz += xv * wih_s[cl * 3 * DF + DF + f];
                    xn += xv * wih_s[cl * 3 * DF + 2 * DF + f];
                }
                r  = sigmoidf_(xr + acc[0][i][ci] + bhh_s[cl]);
                z  = sigmoidf_(xz + acc[1][i][ci] + bhh_s[32 + cl]);
                nn = tanhf(xn + r * (acc[2][i][ci] + bhh_s[64 + cl]));
            } else {
                const size_t xb = ((size_t)row * TT + t) * G3 + col;
                const float xr = xin[xb];
                const float xz = xin[xb + HID];
                const float xn = xin[xb + 2 * HID];
                r  = sigmoidf_(xr + acc[0][i][ci]);
                z  = sigmoidf_(xz + acc[1][i][ci]);
                nn = tanhf(xn + r * (acc[2][i][ci] + bhh_s[64 + cl]));
            }
            const float ho = hin[(size_t)row * HID + col];
            const float hv = (1.f - z) * nn + z * ho;
            hout[(size_t)row * HID + col] = hv;
            uint32_t hi, lo; split_tf32(hv, hi, lo);
            const size_t pidx = hpack_idx(row, col);
            hout_hi[pidx] = __uint_as_float(hi);
            hout_lo[pidx] = __uint_as_float(lo);
            if (LAYER == 0) g_hs[((size_t)row * TT + t) * HID + col] = hv;
        }
    }
}

// ---------------- small kernels ----------------
__global__ void split_mat_packed(const float* __restrict__ in, float* __restrict__ ohi,
                                 float* __restrict__ olo)
{
    const int i = blockIdx.x * 256 + threadIdx.x;
    if (i < G3 * HID) {
        const int gate = i >> 8, k = i & 255;
        uint32_t h, l;
        split_tf32(in[i], h, l);
        const size_t p = wpack_idx(gate, k);
        ohi[p] = __uint_as_float(h);
        olo[p] = __uint_as_float(l);
    }
}

__global__ void bias_combine(const float* __restrict__ bih, const float* __restrict__ bhh,
                             float* __restrict__ out)
{
    const int i = blockIdx.x * 256 + threadIdx.x;
    if (i < G3) out[i] = bih[i] + ((i < 512) ? bhh[i] : 0.f);
}

__global__ void mb_day_mean()
{
    const int b = blockIdx.x, h = threadIdx.x;
    float s = 0.f;
    for (int st = 0; st < 512; st++) s += g_mb[(b * 512 + st) * HID + h];
    g_mbday[b * HID + h] = s * (1.f / 512.f);
}

__global__ void day_topk(const float* __restrict__ thd)
{
    const int b = blockIdx.x;
    const int d = threadIdx.x;
    __shared__ float sim[NDAYS];
    const float* mbd = g_mbday + b * HID;
    float xn = 0.f;
    for (int i = 0; i < HID; i++) { float v = mbd[i]; xn += v * v; }
    xn = sqrtf(xn);
    if (d < NDAYS) {
        const float* yr = thd + d * HID;
        float yn = 0.f, dot = 0.f;
        for (int i = 0; i < HID; i++) { float y = yr[i]; yn += y * y; dot += mbd[i] * y; }
        const float den = xn * sqrtf(yn);
        sim[d] = (den != 0.f) ? dot / den : 0.f;
    }
    __syncthreads();
    if (d == 0) {
        for (int kk = 0; kk < KDAY; kk++) {
            float best = -1e30f; int bi = 0;
            for (int q = 0; q < NDAYS; q++)
                if (sim[q] > best) { best = sim[q]; bi = q; }
            g_dayidx[b * KDAY + kk] = bi;
            sim[bi] = -1e30f;
        }
    }
}

__global__ void make_rowmap()
{
    const int m = blockIdx.x * 256 + threadIdx.x;
    if (m < NSAMP) g_rowmap[m] = g_dayidx[m >> 9] * 512 + (m & 511);
}

__global__ void rownorm256(const float* __restrict__ X, float* __restrict__ out, int R)
{
    const int warp = (blockIdx.x * blockDim.x + threadIdx.x) >> 5;
    const int lane = threadIdx.x & 31;
    if (warp >= R) return;
    const float* r = X + (size_t)warp * HID;
    float s = 0.f;
    for (int i = lane; i < HID; i += 32) { float v = r[i]; s += v * v; }
    #pragma unroll
    for (int o = 16; o > 0; o >>= 1) s += __shfl_xor_sync(0xffffffffu, s, o);
    if (lane == 0) out[warp] = sqrtf(s);
}

__global__ void neigh_topk()
{
    const int n = blockIdx.x;
    const int tid = threadIdx.x;
    const float* row = g_cs + (size_t)n * NSAMP;

    float tv[NNB]; int ti[NNB];
    #pragma unroll
    for (int i = 0; i < NNB; i++) { tv[i] = -1e30f; ti[i] = 0x7fffffff; }

    for (int it = 0; it < NSAMP / 256; it++) {
        const int idx = tid + it * 256;
        const float v = row[idx];
        if (v > tv[NNB - 1]) {
            int p = NNB - 1;
            while (p > 0 && tv[p - 1] < v) { tv[p] = tv[p - 1]; ti[p] = ti[p - 1]; p--; }
            tv[p] = v; ti[p] = idx;
        }
    }

    __shared__ float sval[256 * NNB];
    __shared__ int   sidx[256 * NNB];
    __shared__ float rv[256];
    __shared__ int   rp[256];
    #pragma unroll
    for (int i = 0; i < NNB; i++) { sval[tid * NNB + i] = tv[i]; sidx[tid * NNB + i] = ti[i]; }
    __syncthreads();

    for (int kk = 0; kk < NNB; kk++) {
        float best = -1e30f; int bp = tid * NNB;
        #pragma unroll
        for (int i = 0; i < NNB; i++) {
            const float v = sval[tid * NNB + i];
            if (v > best) { best = v; bp = tid * NNB + i; }
        }
        rv[tid] = best; rp[tid] = bp;
        __syncthreads();
        for (int s = 128; s > 0; s >>= 1) {
            if (tid < s && rv[tid + s] > rv[tid]) { rv[tid] = rv[tid + s]; rp[tid] = rp[tid + s]; }
            __syncthreads();
        }
        if (tid == 0) {
            const int p = rp[0];
            g_vals[n * NNB + kk] = rv[0];
            g_nidx[n * NNB + kk] = sidx[p];
            sval[p] = -1e30f;
        }
        __syncthreads();
    }
}

__global__ void agg_fc(const float* __restrict__ fc_W, const float* __restrict__ fc_b,
                       float* __restrict__ y)
{
    const int n = blockIdx.x, h = threadIdx.x;
    float agg = 0.f;
    #pragma unroll
    for (int k = 0; k < NNB; k++) {
        const float v = g_vals[n * NNB + k] * (1.f / NNB);
        const int id = g_nidx[n * NNB + k];
        agg += v * g_kh[(size_t)id * HID + h];
    }
    float part = fc_W[h] * g_mb[n * HID + h] + fc_W[HID + h] * agg;
    __shared__ float red[256];
    red[h] = part;
    __syncthreads();
    for (int s = 128; s > 0; s >>= 1) {
        if (h < s) red[h] += red[h + s];
        __syncthreads();
    }
    if (h == 0) y[n] = red[0] + fc_b[0];
}

// ---------------- host ----------------
extern "C" void kernel_launch(void* const* d_in, const int* in_sizes, int n_in,
                              void* d_out, int out_size)
{
    const float* inp       = (const float*)d_in[0];
    const float* train_hid = (const float*)d_in[1];
    const float* thd       = (const float*)d_in[2];
    const float* W_ih0     = (const float*)d_in[3];
    const float* W_hh0     = (const float*)d_in[4];
    const float* b_ih0     = (const float*)d_in[5];
    const float* b_hh0     = (const float*)d_in[6];
    const float* W_ih1     = (const float*)d_in[7];
    const float* W_hh1     = (const float*)d_in[8];
    const float* b_ih1     = (const float*)d_in[9];
    const float* b_hh1     = (const float*)d_in[10];
    const float* lin0_W    = (const float*)d_in[11];
    const float* lin0_b    = (const float*)d_in[12];
    const float* lin1_W    = (const float*)d_in[13];
    const float* lin1_b    = (const float*)d_in[14];
    const float* lin2_W    = (const float*)d_in[15];
    const float* lin2_b    = (const float*)d_in[16];
    const float* proj1_W   = (const float*)d_in[17];
    const float* proj2_W   = (const float*)d_in[18];
    const float* fc_W      = (const float*)d_in[19];
    const float* fc_b      = (const float*)d_in[20];
    (void)in_sizes; (void)n_in; (void)out_size;

    float *p_h, *p_hhi, *p_hlo, *p_w0hi, *p_w0lo, *p_w1hi, *p_w1lo;
    float *p_hs, *p_xw1, *p_bias1, *p_mb1, *p_mb2, *p_mb, *p_kh, *p_khn, *p_q, *p_qn, *p_cs;
    int *p_rowmap;
    cudaGetSymbolAddress((void**)&p_h, g_h);
    cudaGetSymbolAddress((void**)&p_hhi, g_hhi);
    cudaGetSymbolAddress((void**)&p_hlo, g_hlo);
    cudaGetSymbolAddress((void**)&p_w0hi, g_w0hi);
    cudaGetSymbolAddress((void**)&p_w0lo, g_w0lo);
    cudaGetSymbolAddress((void**)&p_w1hi, g_w1hi);
    cudaGetSymbolAddress((void**)&p_w1lo, g_w1lo);
    cudaGetSymbolAddress((void**)&p_hs, g_hs);
    cudaGetSymbolAddress((void**)&p_xw1, g_xw1);
    cudaGetSymbolAddress((void**)&p_bias1, g_bias1);
    cudaGetSymbolAddress((void**)&p_mb1, g_mb1);
    cudaGetSymbolAddress((void**)&p_mb2, g_mb2);
    cudaGetSymbolAddress((void**)&p_mb, g_mb);
    cudaGetSymbolAddress((void**)&p_kh, g_kh);
    cudaGetSymbolAddress((void**)&p_khn, g_khn);
    cudaGetSymbolAddress((void**)&p_q, g_q);
    cudaGetSymbolAddress((void**)&p_qn, g_qn);
    cudaGetSymbolAddress((void**)&p_cs, g_cs);
    cudaGetSymbolAddress((void**)&p_rowmap, g_rowmap);

    const int smg = SMG_FLT * 4;
    cudaFuncSetAttribute(gru_v7<0>, cudaFuncAttributeMaxDynamicSharedMemorySize, smg);
    cudaFuncSetAttribute(gru_v7<1>, cudaFuncAttributeMaxDynamicSharedMemorySize, smg);

    const size_t HN = (size_t)BSZ * HID;
    const dim3 gru_grid(HID / GN, BSZ / GM);   // (8, 32)

    // ---- pre-split recurrent weights into frag-packed hi/lo ----
    split_mat_packed<<<(G3 * HID + 255) / 256, 256>>>(W_hh0, p_w0hi, p_w0lo);
    split_mat_packed<<<(G3 * HID + 255) / 256, 256>>>(W_hh1, p_w1hi, p_w1lo);

    // ---- GRU layer 0 ----
    cudaMemsetAsync(p_h, 0, HN * sizeof(float));
    cudaMemsetAsync(p_hhi, 0, HN * sizeof(float));
    cudaMemsetAsync(p_hlo, 0, HN * sizeof(float));
    for (int t = 0; t < TT; t++) {
        const int pr = t & 1, pw = pr ^ 1;
        gru_v7<0><<<gru_grid, 256, smg>>>(
            p_h + pr * HN, p_hhi + pr * HN, p_hlo + pr * HN,
            p_h + pw * HN, p_hhi + pw * HN, p_hlo + pw * HN,
            p_w0hi, p_w0lo, b_hh0, inp, W_ih0, b_ih0, t);
    }

    // ---- layer-1 input gates: one big 3xTF32 GEMM (combined bias) ----
    bias_combine<<<3, 256>>>(b_ih1, b_hh1, p_bias1);
    gemm_x<<<dim3(G3 / XBN, (BSZ * TT) / XBM), 256>>>(p_hs, W_ih1, p_bias1, p_xw1,
                                                      BSZ * TT, G3, HID, 0, nullptr, nullptr, nullptr);

    // ---- GRU layer 1 ----
    cudaMemsetAsync(p_h, 0, HN * sizeof(float));
    cudaMemsetAsync(p_hhi, 0, HN * sizeof(float));
    cudaMemsetAsync(p_hlo, 0, HN * sizeof(float));
    for (int t = 0; t < TT; t++) {
        const int pr = t & 1, pw = pr ^ 1;
        gru_v7<1><<<gru_grid, 256, smg>>>(
            p_h + pr * HN, p_hhi + pr * HN, p_hlo + pr * HN,
            p_h + pw * HN, p_hhi + pw * HN, p_hlo + pw * HN,
            p_w1hi, p_w1lo, b_hh1, p_xw1, nullptr, nullptr, t);
    }
    // t=59 writes parity 0 -> final h at p_h

    // ---- MLP (leaky relu) ----
    gemm_x<<<dim3(512 / XBN, BSZ / XBM), 256>>>(p_h, lin0_W, lin0_b, p_mb1,
                                                BSZ, 512, HID, 1, nullptr, nullptr, nullptr);
    gemm_x<<<dim3(512 / XBN, BSZ / XBM), 256>>>(p_mb1, lin1_W, lin1_b, p_mb2,
                                                BSZ, 512, 512, 1, nullptr, nullptr, nullptr);
    gemm_x<<<dim3(HID / XBN, BSZ / XBM), 256>>>(p_mb2, lin2_W, lin2_b, p_mb,
                                                BSZ, HID, 512, 1, nullptr, nullptr, nullptr);

    // ---- day similarity + gather ----
    mb_day_mean<<<4, HID>>>();
    day_topk<<<4, 256>>>(thd);
    make_rowmap<<<NSAMP / 256, 256>>>();
    gemm_x<<<dim3(HID / XBN, NSAMP / XBM), 256>>>(train_hid, proj2_W, nullptr, p_kh,
                                                  NSAMP, HID, HID, 0, p_rowmap, nullptr, nullptr);
    rownorm256<<<(NSAMP * 32) / 256, 256>>>(p_kh, p_khn, NSAMP);

    // ---- queries + cosine sim + neighbor aggregation ----
    gemm_x<<<dim3(HID / XBN, BSZ / XBM), 256>>>(p_mb, proj1_W, nullptr, p_q,
                                                BSZ, HID, HID, 0, nullptr, nullptr, nullptr);
    rownorm256<<<(BSZ * 32) / 256, 256>>>(p_q, p_qn, BSZ);
    gemm_x<<<dim3(NSAMP / XBN, BSZ / XBM), 256>>>(p_q, p_kh, nullptr, p_cs,
                                                  BSZ, NSAMP, HID, 2, nullptr, p_qn, p_khn);
    neigh_topk<<<BSZ, 256>>>();
    agg_fc<<<BSZ, 256>>>(fc_W, fc_b, (float*)d_out);
}

// round 17
// speedup vs baseline: 1.1209x; 1.0712x over previous
#include <cuda_runtime.h>
#include <cmath>
#include <cstdint>

#define BSZ   2048          // B_DAYS * STOCKS
#define TT    60
#define HID   256
#define G3    768           // 3*HID
#define DF    6
#define NSAMP 20480         // 4 * K_DAY * STOCKS
#define NDAYS 240
#define KDAY  10
#define NNB   10
#define MHS   (BSZ * TT)    // 122880 rows of hs

// ---------------- device scratch (no allocations allowed) ----------------
__device__ float g_h[2 * BSZ * HID];          // ping-pong raw h (row-major)
__device__ float g_hhi[2 * BSZ * HID];        // ping-pong tf32-hi of h (FRAG-PACKED)
__device__ float g_hlo[2 * BSZ * HID];        // ping-pong tf32-lo of h (FRAG-PACKED)
__device__ float g_w0hi[G3 * HID];            // Whh0 hi (FRAG-PACKED wpack)
__device__ float g_w0lo[G3 * HID];
__device__ float g_w1hi[G3 * HID];
__device__ float g_w1lo[G3 * HID];
__device__ float g_wih1hi[G3 * HID];          // W_ih1 packed (wpack)
__device__ float g_wih1lo[G3 * HID];
__device__ float g_hs[(size_t)MHS * HID];     // layer-0 hidden sequence (raw)
__device__ float g_hshi[(size_t)MHS * HID];   // hs packed (hpack)
__device__ float g_hslo[(size_t)MHS * HID];
__device__ float g_xw1[(size_t)MHS * G3];     // layer-1 input gates
__device__ float g_bias1[G3];
__device__ float g_mb1[BSZ * 512];
__device__ float g_mb2[BSZ * 512];
__device__ float g_mb[BSZ * HID];
__device__ float g_mbday[4 * HID];
__device__ int   g_dayidx[4 * KDAY];
__device__ int   g_rowmap[NSAMP];
__device__ float g_kh[NSAMP * HID];
__device__ float g_khhi[NSAMP * HID];         // kh packed (wpack)
__device__ float g_khlo[NSAMP * HID];
__device__ float g_khn[NSAMP];
__device__ float g_q[BSZ * HID];
__device__ float g_qhi[BSZ * HID];            // q packed (hpack)
__device__ float g_qlo[BSZ * HID];
__device__ float g_qn[BSZ];
__device__ float g_cs[(size_t)BSZ * NSAMP];
__device__ float g_vals[BSZ * NNB];
__device__ int   g_nidx[BSZ * NNB];

// ---------------- tf32 helpers ----------------
__device__ __forceinline__ void split_tf32(float x, uint32_t& hi, uint32_t& lo)
{
    uint32_t h;
    asm("cvt.rna.tf32.f32 %0, %1;" : "=r"(h) : "f"(x));
    float rem = x - __uint_as_float(h);
    uint32_t l;
    asm("cvt.rna.tf32.f32 %0, %1;" : "=r"(l) : "f"(rem));
    hi = h; lo = l;
}

__device__ __forceinline__ void mma_tf32(float* d, const uint32_t* a, const uint32_t* b)
{
    asm volatile(
        "mma.sync.aligned.m16n8k8.row.col.f32.tf32.tf32.f32 "
        "{%0,%1,%2,%3}, {%4,%5,%6,%7}, {%8,%9}, {%0,%1,%2,%3};"
        : "+f"(d[0]), "+f"(d[1]), "+f"(d[2]), "+f"(d[3])
        : "r"(a[0]), "r"(a[1]), "r"(a[2]), "r"(a[3]), "r"(b[0]), "r"(b[1]));
}

__device__ __forceinline__ float sigmoidf_(float x) { return 1.f / (1.f + expf(-x)); }

#define CP_ASYNC16(dst, src) \
    asm volatile("cp.async.cg.shared.global [%0], [%1], 16;\n" :: "r"(dst), "l"(src))
#define CP_COMMIT()  asm volatile("cp.async.commit_group;\n")
#define CP_WAIT1()   asm volatile("cp.async.wait_group 1;\n")
#define CP_WAIT0()   asm volatile("cp.async.wait_group 0;\n")

// packed index helpers (K fixed at 256 for all packed operands).
// A-frag pack: 16x8 tile -> lane=(r%8)*4+(c%4), word=((r>>3)&1)+2*((c>>2)&1)
__device__ __forceinline__ size_t hpack_idx(int row, int col)
{
    return ((size_t)(row >> 4) * 32 + (col >> 3)) * 128
         + (((row & 7) << 2) + (col & 3)) * 4
         + ((row >> 3) & 1) + (((col >> 2) & 1) << 1);
}
// B-frag pack: 8(n)x8(k) tile -> lane=(n%8)*4+(k%4), word=(k>>2)&1
__device__ __forceinline__ size_t wpack_idx(int gate, int k)
{
    return ((size_t)(gate >> 3) * 32 + (k >> 3)) * 64
         + (((gate & 7) << 2) + (k & 3)) * 2 + ((k >> 2) & 1);
}

// ---------------- 3xTF32 tensor-core GEMM (in-loop split): C = A @ B^T + bias ----
// act: 0 none, 1 leaky(0.01), 2 cosine-normalize
#define XBM 128
#define XBN 64
#define XBK 32
#define XPAD 36

__global__ void gemm_x(const float* __restrict__ A, const float* __restrict__ B,
                       const float* __restrict__ bias, float* __restrict__ C,
                       int M, int N, int K, int act,
                       const int* __restrict__ rowmap,
                       const float* __restrict__ rnorm, const float* __restrict__ cnorm)
{
    __shared__ float As[XBM][XPAD];
    __shared__ float Bs[XBN][XPAD];
    const int bm = blockIdx.y * XBM;
    const int bn = blockIdx.x * XBN;
    const int tid = threadIdx.x;
    const int warp = tid >> 5, lane = tid & 31;
    const int wm = (warp & 3) * 32;
    const int wn = (warp >> 2) * 32;
    const int g = lane >> 2, tg = lane & 3;

    float acc[2][4][4];
    #pragma unroll
    for (int a = 0; a < 2; a++)
        #pragma unroll
        for (int b = 0; b < 4; b++)
            #pragma unroll
            for (int c = 0; c < 4; c++) acc[a][b][c] = 0.f;

    for (int k0 = 0; k0 < K; k0 += XBK) {
        #pragma unroll
        for (int i = 0; i < 4; i++) {
            int idx = tid + i * 256;
            int r = idx >> 3, c4 = (idx & 7) * 4;
            int arow = bm + r;
            if (rowmap) arow = rowmap[arow];
            float4 v = *(const float4*)(A + (size_t)arow * K + k0 + c4);
            As[r][c4 + 0] = v.x; As[r][c4 + 1] = v.y;
            As[r][c4 + 2] = v.z; As[r][c4 + 3] = v.w;
        }
        #pragma unroll
        for (int i = 0; i < 2; i++) {
            int idx = tid + i * 256;
            int r = idx >> 3, c4 = (idx & 7) * 4;
            float4 v = *(const float4*)(B + (size_t)(bn + r) * K + k0 + c4);
            Bs[r][c4 + 0] = v.x; Bs[r][c4 + 1] = v.y;
            Bs[r][c4 + 2] = v.z; Bs[r][c4 + 3] = v.w;
        }
        __syncthreads();
        #pragma unroll
        for (int kc = 0; kc < 4; kc++) {
            const int kb = kc * 8;
            uint32_t ahi[2][4], alo[2][4];
            #pragma unroll
            for (int mt = 0; mt < 2; mt++) {
                const int r0 = wm + mt * 16;
                split_tf32(As[r0 + g][kb + tg],         ahi[mt][0], alo[mt][0]);
                split_tf32(As[r0 + g + 8][kb + tg],     ahi[mt][1], alo[mt][1]);
                split_tf32(As[r0 + g][kb + tg + 4],     ahi[mt][2], alo[mt][2]);
                split_tf32(As[r0 + g + 8][kb + tg + 4], ahi[mt][3], alo[mt][3]);
            }
            uint32_t bhi[4][2], blo[4][2];
            #pragma unroll
            for (int nt = 0; nt < 4; nt++) {
                const int c0 = wn + nt * 8;
                split_tf32(Bs[c0 + g][kb + tg],     bhi[nt][0], blo[nt][0]);
                split_tf32(Bs[c0 + g][kb + tg + 4], bhi[nt][1], blo[nt][1]);
            }
            #pragma unroll
            for (int mt = 0; mt < 2; mt++)
                #pragma unroll
                for (int nt = 0; nt < 4; nt++) {
                    mma_tf32(acc[mt][nt], alo[mt], bhi[nt]);
                    mma_tf32(acc[mt][nt], ahi[mt], blo[nt]);
                    mma_tf32(acc[mt][nt], ahi[mt], bhi[nt]);
                }
        }
        __syncthreads();
    }

    #pragma unroll
    for (int mt = 0; mt < 2; mt++) {
        #pragma unroll
        for (int nt = 0; nt < 4; nt++) {
            const int r0 = bm + wm + mt * 16 + g;
            const int c0 = bn + wn + nt * 8 + tg * 2;
            #pragma unroll
            for (int ci = 0; ci < 4; ci++) {
                const int m = r0 + ((ci >> 1) ? 8 : 0);
                const int nn = c0 + (ci & 1);
                float v = acc[mt][nt][ci];
                if (bias) v += bias[nn];
                if (act == 1) {
                    v = (v >= 0.f) ? v : 0.01f * v;
                } else if (act == 2) {
                    float den = rnorm[m] * cnorm[nn];
                    v = (den != 0.f) ? v / den : 0.f;
                }
                C[(size_t)m * N + nn] = v;
            }
        }
    }
}

// ---------------- gemm_pk: pure-mma GEMM on pre-packed operands ----------------
// C[M,N] = A[M,256] @ B[N,256]^T (+bias / act). A in hpack hi/lo, B in wpack hi/lo.
// CTA 128x64, 256 thr = 8 warps (4 m-groups x 2 n-halves). K=256, 8 chunks of 32.
#define PSMA 4096           // floats per A buffer per array (8 mt x 4 kt x 128)
#define PSMB 2048           // floats per B buffer per array (8 bt x 4 kt x 64)
#define POFF_AL (2 * PSMA)
#define POFF_BH (4 * PSMA)
#define POFF_BL (4 * PSMA + 2 * PSMB)
#define PSM_FLT (4 * PSMA + 4 * PSMB)   // 24576 floats = 96KB

__device__ __forceinline__ void pk_load_chunk(
    float* sm, const float* __restrict__ ahi, const float* __restrict__ alo,
    const float* __restrict__ bhi, const float* __restrict__ blo,
    int bm, int bn, int ch, int buf, int tid)
{
    const int mt0 = bm >> 4;
    const int bt0 = bn >> 3;
    // A: 1024 float4 per array -> 4 iters of 256
    #pragma unroll
    for (int j = 0; j < 4; j++) {
        int idx = tid + j * 256;
        int mt = idx >> 7, rem = idx & 127;
        int ktl = rem >> 5, f4 = rem & 31;
        size_t g4 = (((size_t)(mt0 + mt) * 32 + (ch * 4 + ktl)) * 32 + f4) * 4;
        uint32_t d1 = (uint32_t)__cvta_generic_to_shared(sm + buf * PSMA + idx * 4);
        CP_ASYNC16(d1, ahi + g4);
        uint32_t d2 = (uint32_t)__cvta_generic_to_shared(sm + POFF_AL + buf * PSMA + idx * 4);
        CP_ASYNC16(d2, alo + g4);
    }
    // B: 512 float4 per array -> 2 iters of 256
    #pragma unroll
    for (int j = 0; j < 2; j++) {
        int idx = tid + j * 256;
        int bt = idx >> 6, rem = idx & 63;
        int ktl = rem >> 4, f4 = rem & 15;
        size_t g4 = (((size_t)(bt0 + bt) * 32 + (ch * 4 + ktl)) * 16 + f4) * 4;
        uint32_t d1 = (uint32_t)__cvta_generic_to_shared(sm + POFF_BH + buf * PSMB + idx * 4);
        CP_ASYNC16(d1, bhi + g4);
        uint32_t d2 = (uint32_t)__cvta_generic_to_shared(sm + POFF_BL + buf * PSMB + idx * 4);
        CP_ASYNC16(d2, blo + g4);
    }
    CP_COMMIT();
}

__global__ void __launch_bounds__(256) gemm_pk(
    const float* __restrict__ ahi, const float* __restrict__ alo,
    const float* __restrict__ bhi, const float* __restrict__ blo,
    const float* __restrict__ bias, float* __restrict__ C,
    int M, int N, int act,
    const float* __restrict__ rnorm, const float* __restrict__ cnorm)
{
    extern __shared__ float sm[];
    const int tid = threadIdx.x;
    const int warp = tid >> 5, lane = tid & 31;
    const int mw = warp >> 1;                // 4 m-groups (2 m-tiles of 16 rows)
    const int nw = warp & 1;                 // 2 n-halves (4 B-frags of 8 cols)
    const int g = lane >> 2, tg = lane & 3;
    const int bn = blockIdx.x * 64;
    const int bm = blockIdx.y * 128;

    pk_load_chunk(sm, ahi, alo, bhi, blo, bm, bn, 0, 0, tid);

    float acc[2][4][4];
    #pragma unroll
    for (int a = 0; a < 2; a++)
        #pragma unroll
        for (int b = 0; b < 4; b++)
            #pragma unroll
            for (int c = 0; c < 4; c++) acc[a][b][c] = 0.f;

    #pragma unroll
    for (int ch = 0; ch < 8; ch++) {
        if (ch < 7) { pk_load_chunk(sm, ahi, alo, bhi, blo, bm, bn, ch + 1, (ch + 1) & 1, tid); CP_WAIT1(); }
        else        { CP_WAIT0(); }
        __syncthreads();

        const float* Ah = sm + (ch & 1) * PSMA;
        const float* Al = sm + POFF_AL + (ch & 1) * PSMA;
        const float* Bh = sm + POFF_BH + (ch & 1) * PSMB;
        const float* Bl = sm + POFF_BL + (ch & 1) * PSMB;

        #pragma unroll
        for (int ks = 0; ks < 4; ks++) {
            uint32_t ah[2][4], al[2][4];
            #pragma unroll
            for (int i = 0; i < 2; i++) {
                const int fa = (((mw * 2 + i) * 4 + ks) * 32 + lane) * 4;
                uint4 vh = *(const uint4*)(Ah + fa);
                uint4 vl = *(const uint4*)(Al + fa);
                ah[i][0] = vh.x; ah[i][1] = vh.y; ah[i][2] = vh.z; ah[i][3] = vh.w;
                al[i][0] = vl.x; al[i][1] = vl.y; al[i][2] = vl.z; al[i][3] = vl.w;
            }
            #pragma unroll
            for (int bt = 0; bt < 4; bt++) {
                const int fo = ((nw * 4 + bt) * 4 + ks) * 64 + lane * 2;
                uint2 vbh = *(const uint2*)(Bh + fo);
                uint2 vbl = *(const uint2*)(Bl + fo);
                uint32_t bh[2] = { vbh.x, vbh.y };
                uint32_t bl[2] = { vbl.x, vbl.y };
                #pragma unroll
                for (int i = 0; i < 2; i++) {
                    mma_tf32(acc[i][bt], al[i], bh);
                    mma_tf32(acc[i][bt], ah[i], bl);
                    mma_tf32(acc[i][bt], ah[i], bh);
                }
            }
        }
        __syncthreads();
    }

    #pragma unroll
    for (int i = 0; i < 2; i++) {
        #pragma unroll
        for (int bt = 0; bt < 4; bt++) {
            #pragma unroll
            for (int ci = 0; ci < 4; ci++) {
                const int row = bm + mw * 32 + i * 16 + g + ((ci >> 1) ? 8 : 0);
                const int col = bn + nw * 32 + bt * 8 + tg * 2 + (ci & 1);
                float v = acc[i][bt][ci];
                if (bias) v += bias[col];
                if (act == 2) {
                    float den = rnorm[row] * cnorm[col];
                    v = (den != 0.f) ? v / den : 0.f;
                }
                C[(size_t)row * N + col] = v;
            }
        }
    }
}

// ---------------- GRU step kernels v7 (unchanged from R14 winner) ----------------
#define GM 64
#define GN 32
#define GK 32

#define SMA 2048
#define SMB 3072
#define OFF_AL (2 * SMA)
#define OFF_BH (4 * SMA)
#define OFF_BL (4 * SMA + 2 * SMB)
#define OFF_EX (4 * SMA + 4 * SMB)
#define SMG_FLT (OFF_EX + 96 + 96 + 32 * 3 * DF + GM * DF)

__device__ __forceinline__ void gru_load_chunk(
    float* sm, const float* __restrict__ hhi, const float* __restrict__ hlo,
    const float* __restrict__ whi, const float* __restrict__ wlo,
    int bm, int bn, int ch, int buf, int tid)
{
    const int mt0 = bm >> 4;
    const int gtb = bn >> 3;
    #pragma unroll
    for (int j = 0; j < 2; j++) {
        int idx = tid + j * 256;
        int mt = idx >> 7, rem = idx & 127;
        int ktl = rem >> 5, ln = rem & 31;
        size_t g4 = (((size_t)(mt0 + mt) * 32 + (ch * 4 + ktl)) * 32 + ln) * 4;
        uint32_t d1 = (uint32_t)__cvta_generic_to_shared(sm + buf * SMA + idx * 4);
        CP_ASYNC16(d1, hhi + g4);
        uint32_t d2 = (uint32_t)__cvta_generic_to_shared(sm + OFF_AL + buf * SMA + idx * 4);
        CP_ASYNC16(d2, hlo + g4);
    }
    #pragma unroll
    for (int j = 0; j < 3; j++) {
        int idx = tid + j * 256;
        int lgt = idx >> 6, rem = idx & 63;
        int ktl = rem >> 4, f4l = rem & 15;
        int gt = (lgt >> 2) * 32 + gtb + (lgt & 3);
        size_t g4 = (((size_t)gt * 32 + (ch * 4 + ktl)) * 16 + f4l) * 4;
        uint32_t d1 = (uint32_t)__cvta_generic_to_shared(sm + OFF_BH + buf * SMB + idx * 4);
        CP_ASYNC16(d1, whi + g4);
        uint32_t d2 = (uint32_t)__cvta_generic_to_shared(sm + OFF_BL + buf * SMB + idx * 4);
        CP_ASYNC16(d2, wlo + g4);
    }
    CP_COMMIT();
}

template<int LAYER>
__global__ void __launch_bounds__(256) gru_v7(
    const float* __restrict__ hin, const float* __restrict__ hin_hi,
    const float* __restrict__ hin_lo, float* __restrict__ hout,
    float* __restrict__ hout_hi, float* __restrict__ hout_lo,
    const float* __restrict__ whi, const float* __restrict__ wlo,
    const float* __restrict__ bhh, const float* __restrict__ xin,
    const float* __restrict__ Wih, const float* __restrict__ bih, int t)
{
    extern __shared__ float sm[];
    float* bih_s = sm + OFF_EX;
    float* bhh_s = bih_s + 96;
    float* wih_s = bhh_s + 96;
    float* xs    = wih_s + 32 * 3 * DF;

    const int tid = threadIdx.x;
    const int warp = tid >> 5, lane = tid & 31;
    const int mw = warp >> 2;
    const int nw = warp & 3;
    const int g = lane >> 2, tg = lane & 3;
    const int bn = blockIdx.x * GN;
    const int bm = blockIdx.y * GM;

    if (tid < 96) {
        const int gg = tid >> 5, c = tid & 31;
        bhh_s[tid] = bhh[gg * HID + bn + c];
        if (LAYER == 0) bih_s[tid] = bih[gg * HID + bn + c];
    }
    if (LAYER == 0) {
        for (int i = tid; i < 32 * 3 * DF; i += 256) {
            const int c = i / (3 * DF), r = i % (3 * DF);
            wih_s[i] = Wih[((r / DF) * HID + bn + c) * DF + (r % DF)];
        }
        for (int i = tid; i < GM * DF; i += 256) {
            const int r = i / DF, f = i % DF;
            xs[i] = xin[(bm + r) * (DF * TT) + f * TT + t];
        }
    }

    gru_load_chunk(sm, hin_hi, hin_lo, whi, wlo, bm, bn, 0, 0, tid);

    float acc[3][2][4];
    #pragma unroll
    for (int a = 0; a < 3; a++)
        #pragma unroll
        for (int b = 0; b < 2; b++)
            #pragma unroll
            for (int d = 0; d < 4; d++) acc[a][b][d] = 0.f;

    #pragma unroll
    for (int ch = 0; ch < 8; ch++) {
        if (ch < 7) { gru_load_chunk(sm, hin_hi, hin_lo, whi, wlo, bm, bn, ch + 1, (ch + 1) & 1, tid); CP_WAIT1(); }
        else        { CP_WAIT0(); }
        __syncthreads();

        const float* Ah = sm + (ch & 1) * SMA;
        const float* Al = sm + OFF_AL + (ch & 1) * SMA;
        const float* Bh = sm + OFF_BH + (ch & 1) * SMB;
        const float* Bl = sm + OFF_BL + (ch & 1) * SMB;

        #pragma unroll
        for (int ks = 0; ks < 4; ks++) {
            uint32_t ah[2][4], al[2][4];
            #pragma unroll
            for (int i = 0; i < 2; i++) {
                const int fa = (((mw * 2 + i) * 4 + ks) * 32 + lane) * 4;
                uint4 vh = *(const uint4*)(Ah + fa);
                uint4 vl = *(const uint4*)(Al + fa);
                ah[i][0] = vh.x; ah[i][1] = vh.y; ah[i][2] = vh.z; ah[i][3] = vh.w;
                al[i][0] = vl.x; al[i][1] = vl.y; al[i][2] = vl.z; al[i][3] = vl.w;
            }
            #pragma unroll
            for (int gg = 0; gg < 3; gg++) {
                const int lgt = gg * 4 + nw;
                const int fo = (lgt * 4 + ks) * 64 + lane * 2;
                uint2 vbh = *(const uint2*)(Bh + fo);
                uint2 vbl = *(const uint2*)(Bl + fo);
                uint32_t bh[2] = { vbh.x, vbh.y };
                uint32_t bl[2] = { vbl.x, vbl.y };
                #pragma unroll
                for (int i = 0; i < 2; i++) {
                    mma_tf32(acc[gg][i], al[i], bh);
                    mma_tf32(acc[gg][i], ah[i], bl);
                    mma_tf32(acc[gg][i], ah[i], bh);
                }
            }
        }
        __syncthreads();
    }

    #pragma unroll
    for (int i = 0; i < 2; i++) {
        #pragma unroll
        for (int ci = 0; ci < 4; ci++) {
            const int rl = mw * 32 + i * 16 + g + ((ci >> 1) ? 8 : 0);
            const int cl = nw * 8 + tg * 2 + (ci & 1);
            const int row = bm + rl, col = bn + cl;
            float r, z, nn;
            if (LAYER == 0) {
                float xr = bih_s[cl], xz = bih_s[32 + cl], xn = bih_s[64 + cl];
                #pragma unroll
                for (int f = 0; f < DF; f++) {
                    const float xv = xs[rl * DF + f];
                    xr += xv * wih_s[cl * 3 * DF + f];
                    xz += xv * wih_s[cl * 3 * DF + DF + f];
                    xn += xv * wih_s[cl * 3 * DF + 2 * DF + f];
                }
                r  = sigmoidf_(xr + acc[0][i][ci] + bhh_s[cl]);
                z  = sigmoidf_(xz + acc[1][i][ci] + bhh_s[32 + cl]);
                nn = tanhf(xn + r * (acc[2][i][ci] + bhh_s[64 + cl]));
            } else {
                const size_t xb = ((size_t)row * TT + t) * G3 + col;
                const float xr = xin[xb];
                const float xz = xin[xb + HID];
                const float xn = xin[xb + 2 * HID];
                r  = sigmoidf_(xr + acc[0][i][ci]);
                z  = sigmoidf_(xz + acc[1][i][ci]);
                nn = tanhf(xn + r * (acc[2][i][ci] + bhh_s[64 + cl]));
            }
            const float ho = hin[(size_t)row * HID + col];
            const float hv = (1.f - z) * nn + z * ho;
            hout[(size_t)row * HID + col] = hv;
            uint32_t hi, lo; split_tf32(hv, hi, lo);
            const size_t pidx = hpack_idx(row, col);
            hout_hi[pidx] = __uint_as_float(hi);
            hout_lo[pidx] = __uint_as_float(lo);
            if (LAYER == 0) g_hs[((size_t)row * TT + t) * HID + col] = hv;
        }
    }
}

// ---------------- small kernels ----------------
__global__ void repack_A(const float* __restrict__ in, float* __restrict__ ohi,
                         float* __restrict__ olo, int M)
{
    const size_t i = (size_t)blockIdx.x * 256 + threadIdx.x;
    if (i < (size_t)M * HID) {
        const int m = (int)(i >> 8), k = (int)(i & 255);
        uint32_t h, l;
        split_tf32(in[i], h, l);
        const size_t p = hpack_idx(m, k);
        ohi[p] = __uint_as_float(h);
        olo[p] = __uint_as_float(l);
    }
}

__global__ void repack_B(const float* __restrict__ in, float* __restrict__ ohi,
                         float* __restrict__ olo, int Nrows)
{
    const size_t i = (size_t)blockIdx.x * 256 + threadIdx.x;
    if (i < (size_t)Nrows * HID) {
        const int n = (int)(i >> 8), k = (int)(i & 255);
        uint32_t h, l;
        split_tf32(in[i], h, l);
        const size_t p = wpack_idx(n, k);
        ohi[p] = __uint_as_float(h);
        olo[p] = __uint_as_float(l);
    }
}

__global__ void bias_combine(const float* __restrict__ bih, const float* __restrict__ bhh,
                             float* __restrict__ out)
{
    const int i = blockIdx.x * 256 + threadIdx.x;
    if (i < G3) out[i] = bih[i] + ((i < 512) ? bhh[i] : 0.f);
}

__global__ void mb_day_mean()
{
    const int b = blockIdx.x, h = threadIdx.x;
    float s = 0.f;
    for (int st = 0; st < 512; st++) s += g_mb[(b * 512 + st) * HID + h];
    g_mbday[b * HID + h] = s * (1.f / 512.f);
}

__global__ void day_topk(const float* __restrict__ thd)
{
    const int b = blockIdx.x;
    const int d = threadIdx.x;
    __shared__ float sim[NDAYS];
    const float* mbd = g_mbday + b * HID;
    float xn = 0.f;
    for (int i = 0; i < HID; i++) { float v = mbd[i]; xn += v * v; }
    xn = sqrtf(xn);
    if (d < NDAYS) {
        const float* yr = thd + d * HID;
        float yn = 0.f, dot = 0.f;
        for (int i = 0; i < HID; i++) { float y = yr[i]; yn += y * y; dot += mbd[i] * y; }
        const float den = xn * sqrtf(yn);
        sim[d] = (den != 0.f) ? dot / den : 0.f;
    }
    __syncthreads();
    if (d == 0) {
        for (int kk = 0; kk < KDAY; kk++) {
            float best = -1e30f; int bi = 0;
            for (int q = 0; q < NDAYS; q++)
                if (sim[q] > best) { best = sim[q]; bi = q; }
            g_dayidx[b * KDAY + kk] = bi;
            sim[bi] = -1e30f;
        }
    }
}

__global__ void make_rowmap()
{
    const int m = blockIdx.x * 256 + threadIdx.x;
    if (m < NSAMP) g_rowmap[m] = g_dayidx[m >> 9] * 512 + (m & 511);
}

__global__ void rownorm256(const float* __restrict__ X, float* __restrict__ out, int R)
{
    const int warp = (blockIdx.x * blockDim.x + threadIdx.x) >> 5;
    const int lane = threadIdx.x & 31;
    if (warp >= R) return;
    const float* r = X + (size_t)warp * HID;
    float s = 0.f;
    for (int i = lane; i < HID; i += 32) { float v = r[i]; s += v * v; }
    #pragma unroll
    for (int o = 16; o > 0; o >>= 1) s += __shfl_xor_sync(0xffffffffu, s, o);
    if (lane == 0) out[warp] = sqrtf(s);
}

__global__ void neigh_topk()
{
    const int n = blockIdx.x;
    const int tid = threadIdx.x;
    const float* row = g_cs + (size_t)n * NSAMP;

    float tv[NNB]; int ti[NNB];
    #pragma unroll
    for (int i = 0; i < NNB; i++) { tv[i] = -1e30f; ti[i] = 0x7fffffff; }

    for (int it = 0; it < NSAMP / 256; it++) {
        const int idx = tid + it * 256;
        const float v = row[idx];
        if (v > tv[NNB - 1]) {
            int p = NNB - 1;
            while (p > 0 && tv[p - 1] < v) { tv[p] = tv[p - 1]; ti[p] = ti[p - 1]; p--; }
            tv[p] = v; ti[p] = idx;
        }
    }

    __shared__ float sval[256 * NNB];
    __shared__ int   sidx[256 * NNB];
    __shared__ float rv[256];
    __shared__ int   rp[256];
    #pragma unroll
    for (int i = 0; i < NNB; i++) { sval[tid * NNB + i] = tv[i]; sidx[tid * NNB + i] = ti[i]; }
    __syncthreads();

    for (int kk = 0; kk < NNB; kk++) {
        float best = -1e30f; int bp = tid * NNB;
        #pragma unroll
        for (int i = 0; i < NNB; i++) {
            const float v = sval[tid * NNB + i];
            if (v > best) { best = v; bp = tid * NNB + i; }
        }
        rv[tid] = best; rp[tid] = bp;
        __syncthreads();
        for (int s = 128; s > 0; s >>= 1) {
            if (tid < s && rv[tid + s] > rv[tid]) { rv[tid] = rv[tid + s]; rp[tid] = rp[tid + s]; }
            __syncthreads();
        }
        if (tid == 0) {
            const int p = rp[0];
            g_vals[n * NNB + kk] = rv[0];
            g_nidx[n * NNB + kk] = sidx[p];
            sval[p] = -1e30f;
        }
        __syncthreads();
    }
}

__global__ void agg_fc(const float* __restrict__ fc_W, const float* __restrict__ fc_b,
                       float* __restrict__ y)
{
    const int n = blockIdx.x, h = threadIdx.x;
    float agg = 0.f;
    #pragma unroll
    for (int k = 0; k < NNB; k++) {
        const float v = g_vals[n * NNB + k] * (1.f / NNB);
        const int id = g_nidx[n * NNB + k];
        agg += v * g_kh[(size_t)id * HID + h];
    }
    float part = fc_W[h] * g_mb[n * HID + h] + fc_W[HID + h] * agg;
    __shared__ float red[256];
    red[h] = part;
    __syncthreads();
    for (int s = 128; s > 0; s >>= 1) {
        if (h < s) red[h] += red[h + s];
        __syncthreads();
    }
    if (h == 0) y[n] = red[0] + fc_b[0];
}

// ---------------- host ----------------
extern "C" void kernel_launch(void* const* d_in, const int* in_sizes, int n_in,
                              void* d_out, int out_size)
{
    const float* inp       = (const float*)d_in[0];
    const float* train_hid = (const float*)d_in[1];
    const float* thd       = (const float*)d_in[2];
    const float* W_ih0     = (const float*)d_in[3];
    const float* W_hh0     = (const float*)d_in[4];
    const float* b_ih0     = (const float*)d_in[5];
    const float* b_hh0     = (const float*)d_in[6];
    const float* W_ih1     = (const float*)d_in[7];
    const float* W_hh1     = (const float*)d_in[8];
    const float* b_ih1     = (const float*)d_in[9];
    const float* b_hh1     = (const float*)d_in[10];
    const float* lin0_W    = (const float*)d_in[11];
    const float* lin0_b    = (const float*)d_in[12];
    const float* lin1_W    = (const float*)d_in[13];
    const float* lin1_b    = (const float*)d_in[14];
    const float* lin2_W    = (const float*)d_in[15];
    const float* lin2_b    = (const float*)d_in[16];
    const float* proj1_W   = (const float*)d_in[17];
    const float* proj2_W   = (const float*)d_in[18];
    const float* fc_W      = (const float*)d_in[19];
    const float* fc_b      = (const float*)d_in[20];
    (void)in_sizes; (void)n_in; (void)out_size;

    float *p_h, *p_hhi, *p_hlo, *p_w0hi, *p_w0lo, *p_w1hi, *p_w1lo, *p_wih1hi, *p_wih1lo;
    float *p_hs, *p_hshi, *p_hslo, *p_xw1, *p_bias1, *p_mb1, *p_mb2, *p_mb;
    float *p_kh, *p_khhi, *p_khlo, *p_khn, *p_q, *p_qhi, *p_qlo, *p_qn, *p_cs;
    int *p_rowmap;
    cudaGetSymbolAddress((void**)&p_h, g_h);
    cudaGetSymbolAddress((void**)&p_hhi, g_hhi);
    cudaGetSymbolAddress((void**)&p_hlo, g_hlo);
    cudaGetSymbolAddress((void**)&p_w0hi, g_w0hi);
    cudaGetSymbolAddress((void**)&p_w0lo, g_w0lo);
    cudaGetSymbolAddress((void**)&p_w1hi, g_w1hi);
    cudaGetSymbolAddress((void**)&p_w1lo, g_w1lo);
    cudaGetSymbolAddress((void**)&p_wih1hi, g_wih1hi);
    cudaGetSymbolAddress((void**)&p_wih1lo, g_wih1lo);
    cudaGetSymbolAddress((void**)&p_hs, g_hs);
    cudaGetSymbolAddress((void**)&p_hshi, g_hshi);
    cudaGetSymbolAddress((void**)&p_hslo, g_hslo);
    cudaGetSymbolAddress((void**)&p_xw1, g_xw1);
    cudaGetSymbolAddress((void**)&p_bias1, g_bias1);
    cudaGetSymbolAddress((void**)&p_mb1, g_mb1);
    cudaGetSymbolAddress((void**)&p_mb2, g_mb2);
    cudaGetSymbolAddress((void**)&p_mb, g_mb);
    cudaGetSymbolAddress((void**)&p_kh, g_kh);
    cudaGetSymbolAddress((void**)&p_khhi, g_khhi);
    cudaGetSymbolAddress((void**)&p_khlo, g_khlo);
    cudaGetSymbolAddress((void**)&p_khn, g_khn);
    cudaGetSymbolAddress((void**)&p_q, g_q);
    cudaGetSymbolAddress((void**)&p_qhi, g_qhi);
    cudaGetSymbolAddress((void**)&p_qlo, g_qlo);
    cudaGetSymbolAddress((void**)&p_qn, g_qn);
    cudaGetSymbolAddress((void**)&p_cs, g_cs);
    cudaGetSymbolAddress((void**)&p_rowmap, g_rowmap);

    const int smg = SMG_FLT * 4;
    const int smp = PSM_FLT * 4;
    cudaFuncSetAttribute(gru_v7<0>, cudaFuncAttributeMaxDynamicSharedMemorySize, smg);
    cudaFuncSetAttribute(gru_v7<1>, cudaFuncAttributeMaxDynamicSharedMemorySize, smg);
    cudaFuncSetAttribute(gemm_pk, cudaFuncAttributeMaxDynamicSharedMemorySize, smp);

    const size_t HN = (size_t)BSZ * HID;
    const dim3 gru_grid(HID / GN, BSZ / GM);   // (8, 32)

    // ---- pre-split weights into frag-packed hi/lo ----
    repack_B<<<(G3 * HID + 255) / 256, 256>>>(W_hh0, p_w0hi, p_w0lo, G3);
    repack_B<<<(G3 * HID + 255) / 256, 256>>>(W_hh1, p_w1hi, p_w1lo, G3);
    repack_B<<<(G3 * HID + 255) / 256, 256>>>(W_ih1, p_wih1hi, p_wih1lo, G3);

    // ---- GRU layer 0 ----
    cudaMemsetAsync(p_h, 0, HN * sizeof(float));
    cudaMemsetAsync(p_hhi, 0, HN * sizeof(float));
    cudaMemsetAsync(p_hlo, 0, HN * sizeof(float));
    for (int t = 0; t < TT; t++) {
        const int pr = t & 1, pw = pr ^ 1;
        gru_v7<0><<<gru_grid, 256, smg>>>(
            p_h + pr * HN, p_hhi + pr * HN, p_hlo + pr * HN,
            p_h + pw * HN, p_hhi + pw * HN, p_hlo + pw * HN,
            p_w0hi, p_w0lo, b_hh0, inp, W_ih0, b_ih0, t);
    }

    // ---- layer-1 input gates: packed pure-mma GEMM ----
    bias_combine<<<3, 256>>>(b_ih1, b_hh1, p_bias1);
    repack_A<<<(int)(((size_t)MHS * HID + 255) / 256), 256>>>(p_hs, p_hshi, p_hslo, MHS);
    gemm_pk<<<dim3(G3 / 64, MHS / 128), 256, smp>>>(p_hshi, p_hslo, p_wih1hi, p_wih1lo,
                                                    p_bias1, p_xw1, MHS, G3, 0, nullptr, nullptr);

    // ---- GRU layer 1 ----
    cudaMemsetAsync(p_h, 0, HN * sizeof(float));
    cudaMemsetAsync(p_hhi, 0, HN * sizeof(float));
    cudaMemsetAsync(p_hlo, 0, HN * sizeof(float));
    for (int t = 0; t < TT; t++) {
        const int pr = t & 1, pw = pr ^ 1;
        gru_v7<1><<<gru_grid, 256, smg>>>(
            p_h + pr * HN, p_hhi + pr * HN, p_hlo + pr * HN,
            p_h + pw * HN, p_hhi + pw * HN, p_hlo + pw * HN,
            p_w1hi, p_w1lo, b_hh1, p_xw1, nullptr, nullptr, t);
    }
    // t=59 writes parity 0 -> final h at p_h

    // ---- MLP (leaky relu) ----
    gemm_x<<<dim3(512 / XBN, BSZ / XBM), 256>>>(p_h, lin0_W, lin0_b, p_mb1,
                                                BSZ, 512, HID, 1, nullptr, nullptr, nullptr);
    gemm_x<<<dim3(512 / XBN, BSZ / XBM), 256>>>(p_mb1, lin1_W, lin1_b, p_mb2,
                                                BSZ, 512, 512, 1, nullptr, nullptr, nullptr);
    gemm_x<<<dim3(HID / XBN, BSZ / XBM), 256>>>(p_mb2, lin2_W, lin2_b, p_mb,
                                                BSZ, HID, 512, 1, nullptr, nullptr, nullptr);

    // ---- day similarity + gather ----
    mb_day_mean<<<4, HID>>>();
    day_topk<<<4, 256>>>(thd);
    make_rowmap<<<NSAMP / 256, 256>>>();
    gemm_x<<<dim3(HID / XBN, NSAMP / XBM), 256>>>(train_hid, proj2_W, nullptr, p_kh,
                                                  NSAMP, HID, HID, 0, p_rowmap, nullptr, nullptr);
    rownorm256<<<(NSAMP * 32) / 256, 256>>>(p_kh, p_khn, NSAMP);
    repack_B<<<(NSAMP * HID + 255) / 256, 256>>>(p_kh, p_khhi, p_khlo, NSAMP);

    // ---- queries + cosine sim (packed pure-mma) + neighbor aggregation ----
    gemm_x<<<dim3(HID / XBN, BSZ / XBM), 256>>>(p_mb, proj1_W, nullptr, p_q,
                                                BSZ, HID, HID, 0, nullptr, nullptr, nullptr);
    rownorm256<<<(BSZ * 32) / 256, 256>>>(p_q, p_qn, BSZ);
    repack_A<<<(BSZ * HID + 255) / 256, 256>>>(p_q, p_qhi, p_qlo, BSZ);
    gemm_pk<<<dim3(NSAMP / 64, BSZ / 128), 256, smp>>>(p_qhi, p_qlo, p_khhi, p_khlo,
                                                       nullptr, p_cs, BSZ, NSAMP, 2, p_qn, p_khn);
    neigh_topk<<<BSZ, 256>>>();
    agg_fc<<<BSZ, 256>>>(fc_W, fc_b, (float*)d_out);
}